// round 10
// baseline (speedup 1.0000x reference)
#include <cuda_runtime.h>
#include <cuda_fp16.h>
#include <math.h>
#include <stdint.h>

#define B_ 8
#define N_ 19
#define T_ 1000
#define D_ 512
#define ALPHA 0.05f
#define LN_EPS 1e-5f
#define ROW_EPS 1e-6f

#define NGRAPH (B_ * T_)       // 8000
#define NROWS (NGRAPH * N_)    // 152000
#define MTILES 1188            // ceil(152000/128)
#define NTILES 4               // 512/128
#define KCHUNKS 8              // 512/64
#define ATILE_BYTES 16384      // 128 rows x 64 k x fp16 (swizzled)
#define BTILE_BYTES 16384      // 128 n   x 64 k x fp16 (swizzled)
#define STAGE_BYTES 32768      // A(16K) + B(16K)
#define NSTAGES 3
#define GEMM_SMEM_DYN (NSTAGES * STAGE_BYTES + 1024)

// ---------------- scratch (__device__ globals; no runtime alloc) ------------
__device__ __align__(16) unsigned char g_a[(size_t)MTILES * KCHUNKS * ATILE_BYTES];
__device__ __align__(16) unsigned char g_b[2 * KCHUNKS * NTILES * BTILE_BYTES];
__device__ float g_adjn[(size_t)NGRAPH * N_ * N_];
__device__ float g_state[(size_t)NROWS * D_];
__device__ float g_y[(size_t)MTILES * 128 * D_];
__device__ int g_cnt[MTILES];   // zero-init; self-resetting per use

// ---------------- helpers ---------------------------------------------------
__device__ __forceinline__ uint32_t swz(uint32_t o) { return o ^ ((o >> 3) & 0x70); }

__device__ __forceinline__ uint32_t smem_u32(const void* p) {
    uint32_t a;
    asm("{ .reg .u64 t; cvta.to.shared.u64 t, %1; cvt.u32.u64 %0, t; }" : "=r"(a) : "l"(p));
    return a;
}
__device__ __forceinline__ void bulk_g2s(uint32_t dst, const void* src,
                                         uint32_t bytes, uint32_t mbar) {
    asm volatile(
        "cp.async.bulk.shared::cta.global.mbarrier::complete_tx::bytes [%0], [%1], %2, [%3];"
        :: "r"(dst), "l"(src), "r"(bytes), "r"(mbar) : "memory");
}
#define MBAR_INIT(a, c) asm volatile("mbarrier.init.shared.b64 [%0], %1;" :: "r"(a), "r"(c) : "memory")
#define MBAR_EXPECT(a, b) asm volatile("mbarrier.arrive.expect_tx.shared.b64 _, [%0], %1;" :: "r"(a), "r"(b) : "memory")
#define MBAR_WAIT(addr, ph) do {                                                      \
    asm volatile(                                                                     \
        "{\n\t.reg .pred P;\n\t"                                                      \
        "WL_%=:\n\t"                                                                  \
        "mbarrier.try_wait.parity.acquire.cta.shared::cta.b64 P, [%0], %1, 0x989680;\n\t" \
        "@P bra.uni WD_%=;\n\t"                                                       \
        "bra.uni WL_%=;\n\t"                                                          \
        "WD_%=:\n\t}"                                                                 \
        :: "r"(addr), "r"(ph) : "memory");                                            \
} while (0)

#define LDX4(r, a)                                                                    \
    asm volatile("ldmatrix.sync.aligned.m8n8.x4.shared.b16 {%0,%1,%2,%3}, [%4];"      \
        : "=r"((r)[0]), "=r"((r)[1]), "=r"((r)[2]), "=r"((r)[3]) : "r"(a))

#define MMA(c, a, b0v, b1v)                                                           \
    asm volatile("mma.sync.aligned.m16n8k16.row.col.f32.f16.f16.f32 "                 \
        "{%0,%1,%2,%3},{%4,%5,%6,%7},{%8,%9},{%0,%1,%2,%3};"                          \
        : "+f"((c)[0]), "+f"((c)[1]), "+f"((c)[2]), "+f"((c)[3])                      \
        : "r"((a)[0]), "r"((a)[1]), "r"((a)[2]), "r"((a)[3]), "r"(b0v), "r"(b1v))

// ---------------- adjacency softplus + row-normalize ------------------------
__global__ __launch_bounds__(128)
void adj_kernel(const float* __restrict__ adjacency,
                const float* __restrict__ edge_w, const float* __restrict__ edge_b)
{
    __shared__ float s[N_][N_];
    int g = blockIdx.x, tid = threadIdx.x;
    float ew = edge_w[0], eb = edge_b[0];
    const float* a = adjacency + (size_t)g * N_ * N_;
    for (int i = tid; i < N_ * N_; i += 128) {
        float v = fmaf(a[i], ew, eb);
        ((float*)s)[i] = fmaxf(v, 0.0f) + log1pf(expf(-fabsf(v)));
    }
    __syncthreads();
    if (tid < N_) {
        float sum = 0.0f;
        #pragma unroll
        for (int j = 0; j < N_; j++) sum += s[tid][j];
        float inv = 1.0f / (sum + ROW_EPS);
        #pragma unroll
        for (int j = 0; j < N_; j++) s[tid][j] *= inv;
    }
    __syncthreads();
    for (int i = tid; i < N_ * N_; i += 128)
        g_adjn[(size_t)g * N_ * N_ + i] = ((float*)s)[i];
}

// ---------------- W -> fp16 W^T tiles (n-major, swizzled) -------------------
__global__ __launch_bounds__(256)
void wconv_kernel(const float* __restrict__ W)
{
    int p = blockIdx.x * 256 + threadIdx.x;
    if (p >= 2 * 512 * 64) return;
    int l = p >> 15;
    int rem = p & 32767;
    int n = rem >> 6;
    int k8 = rem & 63;
    int k0 = k8 * 8;
    const float* src = W + (size_t)l * D_ * D_ + n;
    union { uint4 q; __half h[8]; } H;
    #pragma unroll
    for (int i = 0; i < 8; i++)
        H.h[i] = __float2half_rn(src[(size_t)(k0 + i) * D_]);
    int kchunk = k0 >> 6, nq = n >> 7, nl = n & 127, kl = k0 & 63;
    size_t blk = (size_t)l * (KCHUNKS * NTILES) + kchunk * NTILES + nq;
    uint32_t off = swz((uint32_t)(nl * 128 + kl * 2));
    *(uint4*)(g_b + blk * BTILE_BYTES + off) = H.q;
}

// ---------------- mixing: x (src) -> fp16 A tiles ---------------------------
__global__ __launch_bounds__(256)
void mix_kernel(const float* __restrict__ src, int transposed)
{
    __shared__ float xs[N_][D_];
    __shared__ float sadj[N_][N_];
    int g = blockIdx.x, tid = threadIdx.x;
    for (int i = tid; i < N_ * N_; i += 256)
        ((float*)sadj)[i] = g_adjn[(size_t)g * N_ * N_ + i];
    long tb = 0;
    if (transposed) {
        int bb = g / T_, tt = g - bb * T_;
        tb = (long)bb * N_ * T_ * D_ + (long)tt * D_;
    }
    for (int idx = tid; idx < N_ * D_; idx += 256) {
        int n = idx >> 9, d = idx & (D_ - 1);
        xs[n][d] = transposed ? src[tb + (long)n * T_ * D_ + d]
                              : src[((long)g * N_ + n) * D_ + d];
    }
    __syncthreads();
    for (int task = tid; task < N_ * 64; task += 256) {
        int n = task >> 6, k8 = task & 63, d0 = k8 << 3;
        float m[8];
        #pragma unroll
        for (int i = 0; i < 8; i++) m[i] = (1.0f - ALPHA) * xs[n][d0 + i];
        #pragma unroll
        for (int j = 0; j < N_; j++) {
            float a = ALPHA * sadj[n][j];
            #pragma unroll
            for (int i = 0; i < 8; i++) m[i] = fmaf(a, xs[j][d0 + i], m[i]);
        }
        union { uint4 q; __half h[8]; } H;
        #pragma unroll
        for (int i = 0; i < 8; i++) H.h[i] = __float2half_rn(m[i]);
        int r = g * N_ + n;
        int mt = r >> 7, rl = r & 127;
        size_t blk = (size_t)mt * KCHUNKS + (k8 >> 3);
        uint32_t off = swz((uint32_t)(rl * 128 + (k8 & 7) * 16));
        *(uint4*)(g_a + blk * ATILE_BYTES + off) = H.q;
    }
}

// ---------------- GEMM 128x128 + last-CTA fused LN epilogue -----------------
// After y stores, each of the 4 nt-CTAs per mtile increments cnt[mtile];
// the 4th re-reads the 128x512 y slab (L2-hot), applies bias+residual+LN+GELU,
// and writes the final destination. Numerically identical to separate ln pass.
__global__ __launch_bounds__(256, 2)
void gemm_kernel(const unsigned char* __restrict__ gA,
                 const unsigned char* __restrict__ gB,
                 float* __restrict__ y,
                 const float* __restrict__ res, int res_trans,
                 float* __restrict__ dst, int dst_trans,
                 const float* __restrict__ gamma, const float* __restrict__ beta,
                 const float* __restrict__ bias,
                 int* __restrict__ cnt)
{
    extern __shared__ unsigned char smraw[];
    __shared__ __align__(8) unsigned long long s_mbar[NSTAGES];
    __shared__ int s_last;

    const int tid = threadIdx.x, wid = tid >> 5, lane = tid & 31;
    const int wm = wid >> 1, wn = wid & 1;
    const int mtile = blockIdx.x >> 2, nt = blockIdx.x & 3;

    const uint32_t base = (smem_u32(smraw) + 1023) & ~1023u;
    uint32_t mb[NSTAGES];
    #pragma unroll
    for (int i = 0; i < NSTAGES; i++) mb[i] = smem_u32(&s_mbar[0]) + 8 * i;
    if (tid == 0)
        for (int i = 0; i < NSTAGES; i++) MBAR_INIT(mb[i], 1);
    __syncthreads();

    const unsigned char* pA = gA + (size_t)mtile * KCHUNKS * ATILE_BYTES;
    const unsigned char* pB = gB + (size_t)nt * BTILE_BYTES;

    const uint32_t a_rowoff = (wm * 32 + (lane & 15)) * 128;
    const uint32_t a_klane = (uint32_t)(lane >> 4) << 4;
    const uint32_t b_rowoff = (wn * 64 + ((lane >> 4) << 3) + (lane & 7)) * 128;
    const uint32_t b_klane = (uint32_t)((lane >> 3) & 1) << 4;
    const uint32_t cswz = (uint32_t)(lane & 7) << 4;

    float acc[2][8][4];
    #pragma unroll
    for (int ms = 0; ms < 2; ms++)
        #pragma unroll
        for (int ns = 0; ns < 8; ns++)
            #pragma unroll
            for (int q = 0; q < 4; q++) acc[ms][ns][q] = 0.0f;

    if (tid == 0) {
        #pragma unroll
        for (int s = 0; s < 2; s++) {
            const uint32_t st = base + s * STAGE_BYTES;
            MBAR_EXPECT(mb[s], (uint32_t)STAGE_BYTES);
            bulk_g2s(st,         pA + (size_t)s * ATILE_BYTES, ATILE_BYTES, mb[s]);
            bulk_g2s(st + 16384, pB + (size_t)s * NTILES * BTILE_BYTES, BTILE_BYTES, mb[s]);
        }
    }

    for (int kc = 0; kc < KCHUNKS; kc++) {
        const int slot = kc % NSTAGES;
        MBAR_WAIT(mb[slot], (kc / NSTAGES) & 1);
        __syncthreads();
        if (tid == 0 && kc + 2 < KCHUNKS) {
            const int kn = kc + 2, sl = kn % NSTAGES;
            const uint32_t st = base + sl * STAGE_BYTES;
            MBAR_EXPECT(mb[sl], (uint32_t)STAGE_BYTES);
            bulk_g2s(st,         pA + (size_t)kn * ATILE_BYTES, ATILE_BYTES, mb[sl]);
            bulk_g2s(st + 16384, pB + (size_t)kn * NTILES * BTILE_BYTES, BTILE_BYTES, mb[sl]);
        }
        const uint32_t st = base + slot * STAGE_BYTES;
        const uint32_t sA = st, sB = st + 16384;

        #pragma unroll
        for (int ks = 0; ks < 4; ks++) {
            const uint32_t akb = ((uint32_t)(ks * 32) + a_klane) ^ cswz;
            const uint32_t bkb = ((uint32_t)(ks * 32) + b_klane) ^ cswz;
            uint32_t av[2][4];
            LDX4(av[0], sA + a_rowoff + akb);
            LDX4(av[1], sA + a_rowoff + 2048 + akb);
            uint32_t bv[4][4];
            #pragma unroll
            for (int nb = 0; nb < 4; nb++)
                LDX4(bv[nb], sB + b_rowoff + nb * 2048 + bkb);
            #pragma unroll
            for (int ms = 0; ms < 2; ms++) {
                #pragma unroll
                for (int ns = 0; ns < 8; ns++) {
                    const uint32_t* BB = &bv[ns >> 1][(ns & 1) * 2];
                    MMA(acc[ms][ns], av[ms], BB[0], BB[1]);
                }
            }
        }
    }

    // ---- y stores --------------------------------------------------------
    const int mrow = mtile * 128 + wm * 32;
    const int ncol = nt * 128 + wn * 64;
    #pragma unroll
    for (int ms = 0; ms < 2; ms++) {
        const int r0 = mrow + ms * 16 + (lane >> 2);
        const int r1 = r0 + 8;
        #pragma unroll
        for (int ns = 0; ns < 8; ns++) {
            const int c = ncol + ns * 8 + (lane & 3) * 2;
            if (r0 < NROWS)
                *(float2*)(y + (size_t)r0 * D_ + c) = make_float2(acc[ms][ns][0], acc[ms][ns][1]);
            if (r1 < NROWS)
                *(float2*)(y + (size_t)r1 * D_ + c) = make_float2(acc[ms][ns][2], acc[ms][ns][3]);
        }
    }

    // ---- last-CTA election -------------------------------------------------
    __threadfence();
    if (tid == 0) {
        int old = atomicAdd(&cnt[mtile], 1);
        if (old == 3) { cnt[mtile] = 0; s_last = 1; }
        else s_last = 0;
    }
    __syncthreads();
    if (!s_last) return;
    __threadfence();

    // ---- fused LN epilogue: 8 warps x 16 rows (y slab is L2-hot) ----------
    for (int r = wid; r < 128; r += 8) {
        const int row = mtile * 128 + r;
        if (row >= NROWS) continue;
        long toff = 0;
        if (res_trans | dst_trans) {
            int g = row / N_, n = row - g * N_;
            int bb = g / T_, tt = g - bb * T_;
            toff = ((long)(bb * N_ + n) * T_ + tt) * D_;
        }
        const float* rp = res + (res_trans ? toff : (long)row * D_);
        float* dp = dst + (dst_trans ? toff : (long)row * D_);
        const float* yp = y + (long)row * D_;

        float v[16];
        float sum = 0.0f, sq = 0.0f;
        #pragma unroll
        for (int i = 0; i < 4; i++) {
            int c = lane * 4 + i * 128;
            float4 a = *(const float4*)(yp + c);
            float4 r4 = *(const float4*)(rp + c);
            float4 b4 = *(const float4*)(bias + c);
            float t0 = a.x + b4.x + r4.x, t1 = a.y + b4.y + r4.y;
            float t2 = a.z + b4.z + r4.z, t3 = a.w + b4.w + r4.w;
            v[i*4+0] = t0; v[i*4+1] = t1; v[i*4+2] = t2; v[i*4+3] = t3;
            sum += t0 + t1 + t2 + t3;
            sq = fmaf(t0, t0, sq); sq = fmaf(t1, t1, sq);
            sq = fmaf(t2, t2, sq); sq = fmaf(t3, t3, sq);
        }
        #pragma unroll
        for (int o = 16; o; o >>= 1) {
            sum += __shfl_xor_sync(0xffffffffu, sum, o);
            sq  += __shfl_xor_sync(0xffffffffu, sq, o);
        }
        float mu = sum * (1.0f / D_);
        float var = sq * (1.0f / D_) - mu * mu;
        float rstd = rsqrtf(var + LN_EPS);
        #pragma unroll
        for (int i = 0; i < 4; i++) {
            int c = lane * 4 + i * 128;
            float4 g4 = *(const float4*)(gamma + c);
            float4 be4 = *(const float4*)(beta + c);
            float o0 = fmaf((v[i*4+0] - mu) * rstd, g4.x, be4.x);
            float o1 = fmaf((v[i*4+1] - mu) * rstd, g4.y, be4.y);
            float o2 = fmaf((v[i*4+2] - mu) * rstd, g4.z, be4.z);
            float o3 = fmaf((v[i*4+3] - mu) * rstd, g4.w, be4.w);
            o0 = 0.5f * o0 * (1.0f + erff(o0 * 0.70710678118654752f));
            o1 = 0.5f * o1 * (1.0f + erff(o1 * 0.70710678118654752f));
            o2 = 0.5f * o2 * (1.0f + erff(o2 * 0.70710678118654752f));
            o3 = 0.5f * o3 * (1.0f + erff(o3 * 0.70710678118654752f));
            *(float4*)(dp + c) = make_float4(o0, o1, o2, o3);
        }
    }
}

// ---------------- launch -----------------------------------------------------
extern "C" void kernel_launch(void* const* d_in, const int* in_sizes, int n_in,
                              void* d_out, int out_size)
{
    const float* features  = (const float*)d_in[0];
    const float* adjacency = (const float*)d_in[1];
    const float* edge_w    = (const float*)d_in[2];
    const float* edge_b    = (const float*)d_in[3];
    const float* W         = (const float*)d_in[4];
    const float* bias      = (const float*)d_in[5];
    const float* gamma     = (const float*)d_in[6];
    const float* beta      = (const float*)d_in[7];
    float* out = (float*)d_out;

    unsigned char *av, *bv;
    float *yv, *state;
    int *cnt;
    cudaGetSymbolAddress((void**)&av, g_a);
    cudaGetSymbolAddress((void**)&bv, g_b);
    cudaGetSymbolAddress((void**)&yv, g_y);
    cudaGetSymbolAddress((void**)&state, g_state);
    cudaGetSymbolAddress((void**)&cnt, g_cnt);

    cudaFuncSetAttribute(gemm_kernel, cudaFuncAttributeMaxDynamicSharedMemorySize,
                         GEMM_SMEM_DYN);

    adj_kernel<<<NGRAPH, 128>>>(adjacency, edge_w, edge_b);
    wconv_kernel<<<256, 256>>>(W);

    const size_t bl = (size_t)KCHUNKS * NTILES * BTILE_BYTES;

    // layer 0: gemm epilogue does LN -> writes state (row-major)
    mix_kernel<<<NGRAPH, 256>>>(features, 1);
    gemm_kernel<<<MTILES * NTILES, 256, GEMM_SMEM_DYN>>>(
        av, bv, yv, features, 1, state, 0, gamma, beta, bias, cnt);
    // layer 1: mix from state; gemm epilogue writes final out (transposed)
    mix_kernel<<<NGRAPH, 256>>>(state, 0);
    gemm_kernel<<<MTILES * NTILES, 256, GEMM_SMEM_DYN>>>(
        av, bv + bl, yv, state, 0, out, 1, gamma + D_, beta + D_, bias + D_, cnt);
}

// round 11
// speedup vs baseline: 1.1798x; 1.1798x over previous
#include <cuda_runtime.h>
#include <cuda_fp16.h>
#include <math.h>
#include <stdint.h>

#define B_ 8
#define N_ 19
#define T_ 1000
#define D_ 512
#define ALPHA 0.05f
#define LN_EPS 1e-5f
#define ROW_EPS 1e-6f

#define NGRAPH (B_ * T_)       // 8000
#define NROWS (NGRAPH * N_)    // 152000
#define MTILES 1188            // ceil(152000/128)
#define NTILES 4               // 512/128
#define KCHUNKS 8              // 512/64
#define ATILE_BYTES 16384      // 128 rows x 64 k x fp16 (swizzled)
#define BTILE_BYTES 16384      // 128 n   x 64 k x fp16 (swizzled)
#define STAGE_BYTES 32768      // A(16K) + B(16K)
#define NSTAGES 3
#define GEMM_SMEM_DYN (NSTAGES * STAGE_BYTES + 1024)

// ---------------- scratch (__device__ globals; no runtime alloc) ------------
__device__ __align__(16) unsigned char g_a[(size_t)MTILES * KCHUNKS * ATILE_BYTES];
__device__ __align__(16) unsigned char g_b[2 * KCHUNKS * NTILES * BTILE_BYTES];
__device__ float g_adjn[(size_t)NGRAPH * N_ * N_];
__device__ float g_state[(size_t)NROWS * D_];
__device__ float g_y[(size_t)MTILES * 128 * D_];

// ---------------- helpers ---------------------------------------------------
__device__ __forceinline__ uint32_t swz(uint32_t o) { return o ^ ((o >> 3) & 0x70); }

__device__ __forceinline__ uint32_t smem_u32(const void* p) {
    uint32_t a;
    asm("{ .reg .u64 t; cvta.to.shared.u64 t, %1; cvt.u32.u64 %0, t; }" : "=r"(a) : "l"(p));
    return a;
}
__device__ __forceinline__ void bulk_g2s(uint32_t dst, const void* src,
                                         uint32_t bytes, uint32_t mbar) {
    asm volatile(
        "cp.async.bulk.shared::cta.global.mbarrier::complete_tx::bytes [%0], [%1], %2, [%3];"
        :: "r"(dst), "l"(src), "r"(bytes), "r"(mbar) : "memory");
}
#define MBAR_INIT(a, c) asm volatile("mbarrier.init.shared.b64 [%0], %1;" :: "r"(a), "r"(c) : "memory")
#define MBAR_EXPECT(a, b) asm volatile("mbarrier.arrive.expect_tx.shared.b64 _, [%0], %1;" :: "r"(a), "r"(b) : "memory")
#define MBAR_WAIT(addr, ph) do {                                                      \
    asm volatile(                                                                     \
        "{\n\t.reg .pred P;\n\t"                                                      \
        "WL_%=:\n\t"                                                                  \
        "mbarrier.try_wait.parity.acquire.cta.shared::cta.b64 P, [%0], %1, 0x989680;\n\t" \
        "@P bra.uni WD_%=;\n\t"                                                       \
        "bra.uni WL_%=;\n\t"                                                          \
        "WD_%=:\n\t}"                                                                 \
        :: "r"(addr), "r"(ph) : "memory");                                            \
} while (0)

#define LDX4(r, a)                                                                    \
    asm volatile("ldmatrix.sync.aligned.m8n8.x4.shared.b16 {%0,%1,%2,%3}, [%4];"      \
        : "=r"((r)[0]), "=r"((r)[1]), "=r"((r)[2]), "=r"((r)[3]) : "r"(a))

#define MMA(c, a, b0v, b1v)                                                           \
    asm volatile("mma.sync.aligned.m16n8k16.row.col.f32.f16.f16.f32 "                 \
        "{%0,%1,%2,%3},{%4,%5,%6,%7},{%8,%9},{%0,%1,%2,%3};"                          \
        : "+f"((c)[0]), "+f"((c)[1]), "+f"((c)[2]), "+f"((c)[3])                      \
        : "r"((a)[0]), "r"((a)[1]), "r"((a)[2]), "r"((a)[3]), "r"(b0v), "r"(b1v))

// ---------------- adjacency softplus + row-normalize ------------------------
__global__ __launch_bounds__(128)
void adj_kernel(const float* __restrict__ adjacency,
                const float* __restrict__ edge_w, const float* __restrict__ edge_b)
{
    __shared__ float s[N_][N_];
    int g = blockIdx.x, tid = threadIdx.x;
    float ew = edge_w[0], eb = edge_b[0];
    const float* a = adjacency + (size_t)g * N_ * N_;
    for (int i = tid; i < N_ * N_; i += 128) {
        float v = fmaf(a[i], ew, eb);
        ((float*)s)[i] = fmaxf(v, 0.0f) + log1pf(expf(-fabsf(v)));
    }
    __syncthreads();
    if (tid < N_) {
        float sum = 0.0f;
        #pragma unroll
        for (int j = 0; j < N_; j++) sum += s[tid][j];
        float inv = 1.0f / (sum + ROW_EPS);
        #pragma unroll
        for (int j = 0; j < N_; j++) s[tid][j] *= inv;
    }
    __syncthreads();
    for (int i = tid; i < N_ * N_; i += 128)
        g_adjn[(size_t)g * N_ * N_ + i] = ((float*)s)[i];
}

// ---------------- W -> fp16 W^T tiles (n-major, swizzled) -------------------
__global__ __launch_bounds__(256)
void wconv_kernel(const float* __restrict__ W)
{
    int p = blockIdx.x * 256 + threadIdx.x;
    if (p >= 2 * 512 * 64) return;
    int l = p >> 15;
    int rem = p & 32767;
    int n = rem >> 6;
    int k8 = rem & 63;
    int k0 = k8 * 8;
    const float* src = W + (size_t)l * D_ * D_ + n;
    union { uint4 q; __half h[8]; } H;
    #pragma unroll
    for (int i = 0; i < 8; i++)
        H.h[i] = __float2half_rn(src[(size_t)(k0 + i) * D_]);
    int kchunk = k0 >> 6, nq = n >> 7, nl = n & 127, kl = k0 & 63;
    size_t blk = (size_t)l * (KCHUNKS * NTILES) + kchunk * NTILES + nq;
    uint32_t off = swz((uint32_t)(nl * 128 + kl * 2));
    *(uint4*)(g_b + blk * BTILE_BYTES + off) = H.q;
}

// ---------------- shared mixing routine (operates on xs in smem) ------------
__device__ __forceinline__ void do_mix_split(const float (*xs)[D_],
                                             const float (*sadj)[N_],
                                             int g, int tid)
{
    for (int task = tid; task < N_ * 64; task += 256) {
        int n = task >> 6, k8 = task & 63, d0 = k8 << 3;
        float m[8];
        #pragma unroll
        for (int i = 0; i < 8; i++) m[i] = (1.0f - ALPHA) * xs[n][d0 + i];
        #pragma unroll
        for (int j = 0; j < N_; j++) {
            float a = ALPHA * sadj[n][j];
            #pragma unroll
            for (int i = 0; i < 8; i++) m[i] = fmaf(a, xs[j][d0 + i], m[i]);
        }
        union { uint4 q; __half h[8]; } H;
        #pragma unroll
        for (int i = 0; i < 8; i++) H.h[i] = __float2half_rn(m[i]);
        int r = g * N_ + n;
        int mt = r >> 7, rl = r & 127;
        size_t blk = (size_t)mt * KCHUNKS + (k8 >> 3);
        uint32_t off = swz((uint32_t)(rl * 128 + (k8 & 7) * 16));
        *(uint4*)(g_a + blk * ATILE_BYTES + off) = H.q;
    }
}

// ---------------- layer-0 mix: features -> A tiles ---------------------------
__global__ __launch_bounds__(256)
void mix_kernel(const float* __restrict__ src)
{
    __shared__ float xs[N_][D_];
    __shared__ float sadj[N_][N_];
    int g = blockIdx.x, tid = threadIdx.x;
    for (int i = tid; i < N_ * N_; i += 256)
        ((float*)sadj)[i] = g_adjn[(size_t)g * N_ * N_ + i];
    int bb = g / T_, tt = g - bb * T_;
    long tb = (long)bb * N_ * T_ * D_ + (long)tt * D_;
    for (int idx = tid; idx < N_ * D_; idx += 256) {
        int n = idx >> 9, d = idx & (D_ - 1);
        xs[n][d] = src[tb + (long)n * T_ * D_ + d];
    }
    __syncthreads();
    do_mix_split(xs, sadj, g, tid);
}

// ---------------- fused: layer-0 LN/GELU + layer-1 mix ----------------------
// y already contains mma + bias + residual (folded in gemm epilogue).
__global__ __launch_bounds__(256)
void lnmix_kernel(const float* __restrict__ y,
                  const float* __restrict__ gamma, const float* __restrict__ beta)
{
    __shared__ float xs[N_][D_];
    __shared__ float sadj[N_][N_];
    int g = blockIdx.x, tid = threadIdx.x;
    int wid = tid >> 5, lane = tid & 31;
    for (int i = tid; i < N_ * N_; i += 256)
        ((float*)sadj)[i] = g_adjn[(size_t)g * N_ * N_ + i];

    for (int r = wid; r < N_; r += 8) {
        const long row = (long)g * N_ + r;
        const float* yp = y + row * D_;
        float v[16];
        float sum = 0.0f, sq = 0.0f;
        #pragma unroll
        for (int i = 0; i < 4; i++) {
            int c = lane * 4 + i * 128;
            float4 a = *(const float4*)(yp + c);
            v[i*4+0] = a.x; v[i*4+1] = a.y; v[i*4+2] = a.z; v[i*4+3] = a.w;
            sum += a.x + a.y + a.z + a.w;
            sq = fmaf(a.x, a.x, sq); sq = fmaf(a.y, a.y, sq);
            sq = fmaf(a.z, a.z, sq); sq = fmaf(a.w, a.w, sq);
        }
        #pragma unroll
        for (int o = 16; o; o >>= 1) {
            sum += __shfl_xor_sync(0xffffffffu, sum, o);
            sq  += __shfl_xor_sync(0xffffffffu, sq, o);
        }
        float mu = sum * (1.0f / D_);
        float var = sq * (1.0f / D_) - mu * mu;
        float rstd = rsqrtf(var + LN_EPS);
        float* sp = g_state + row * D_;
        #pragma unroll
        for (int i = 0; i < 4; i++) {
            int c = lane * 4 + i * 128;
            float4 g4 = *(const float4*)(gamma + c);
            float4 be4 = *(const float4*)(beta + c);
            float o0 = fmaf((v[i*4+0] - mu) * rstd, g4.x, be4.x);
            float o1 = fmaf((v[i*4+1] - mu) * rstd, g4.y, be4.y);
            float o2 = fmaf((v[i*4+2] - mu) * rstd, g4.z, be4.z);
            float o3 = fmaf((v[i*4+3] - mu) * rstd, g4.w, be4.w);
            o0 = 0.5f * o0 * (1.0f + erff(o0 * 0.70710678118654752f));
            o1 = 0.5f * o1 * (1.0f + erff(o1 * 0.70710678118654752f));
            o2 = 0.5f * o2 * (1.0f + erff(o2 * 0.70710678118654752f));
            o3 = 0.5f * o3 * (1.0f + erff(o3 * 0.70710678118654752f));
            xs[r][c] = o0; xs[r][c+1] = o1; xs[r][c+2] = o2; xs[r][c+3] = o3;
            *(float4*)(sp + c) = make_float4(o0, o1, o2, o3);
        }
    }
    __syncthreads();
    do_mix_split(xs, sadj, g, tid);
}

// ---------------- GEMM: 128x128, single fp16 term, bias+residual folded -----
__global__ __launch_bounds__(256, 2)
void gemm_kernel(const unsigned char* __restrict__ gA,
                 const unsigned char* __restrict__ gB,
                 float* __restrict__ y,
                 const float* __restrict__ res, int res_trans,
                 const float* __restrict__ bias)
{
    extern __shared__ unsigned char smraw[];
    __shared__ __align__(8) unsigned long long s_mbar[NSTAGES];
    __shared__ float sBias[128];

    const int tid = threadIdx.x, wid = tid >> 5, lane = tid & 31;
    const int wm = wid >> 1, wn = wid & 1;
    const int mtile = blockIdx.x >> 2, nt = blockIdx.x & 3;

    const uint32_t base = (smem_u32(smraw) + 1023) & ~1023u;
    uint32_t mb[NSTAGES];
    #pragma unroll
    for (int i = 0; i < NSTAGES; i++) mb[i] = smem_u32(&s_mbar[0]) + 8 * i;
    if (tid == 0)
        for (int i = 0; i < NSTAGES; i++) MBAR_INIT(mb[i], 1);
    if (tid < 128) sBias[tid] = bias[nt * 128 + tid];
    __syncthreads();

    const unsigned char* pA = gA + (size_t)mtile * KCHUNKS * ATILE_BYTES;
    const unsigned char* pB = gB + (size_t)nt * BTILE_BYTES;

    const uint32_t a_rowoff = (wm * 32 + (lane & 15)) * 128;
    const uint32_t a_klane = (uint32_t)(lane >> 4) << 4;
    const uint32_t b_rowoff = (wn * 64 + ((lane >> 4) << 3) + (lane & 7)) * 128;
    const uint32_t b_klane = (uint32_t)((lane >> 3) & 1) << 4;
    const uint32_t cswz = (uint32_t)(lane & 7) << 4;

    float acc[2][8][4];
    #pragma unroll
    for (int ms = 0; ms < 2; ms++)
        #pragma unroll
        for (int ns = 0; ns < 8; ns++)
            #pragma unroll
            for (int q = 0; q < 4; q++) acc[ms][ns][q] = 0.0f;

    if (tid == 0) {
        #pragma unroll
        for (int s = 0; s < 2; s++) {
            const uint32_t st = base + s * STAGE_BYTES;
            MBAR_EXPECT(mb[s], (uint32_t)STAGE_BYTES);
            bulk_g2s(st,         pA + (size_t)s * ATILE_BYTES, ATILE_BYTES, mb[s]);
            bulk_g2s(st + 16384, pB + (size_t)s * NTILES * BTILE_BYTES, BTILE_BYTES, mb[s]);
        }
    }

    for (int kc = 0; kc < KCHUNKS; kc++) {
        const int slot = kc % NSTAGES;
        MBAR_WAIT(mb[slot], (kc / NSTAGES) & 1);
        __syncthreads();
        if (tid == 0 && kc + 2 < KCHUNKS) {
            const int kn = kc + 2, sl = kn % NSTAGES;
            const uint32_t st = base + sl * STAGE_BYTES;
            MBAR_EXPECT(mb[sl], (uint32_t)STAGE_BYTES);
            bulk_g2s(st,         pA + (size_t)kn * ATILE_BYTES, ATILE_BYTES, mb[sl]);
            bulk_g2s(st + 16384, pB + (size_t)kn * NTILES * BTILE_BYTES, BTILE_BYTES, mb[sl]);
        }
        const uint32_t st = base + slot * STAGE_BYTES;
        const uint32_t sA = st, sB = st + 16384;

        #pragma unroll
        for (int ks = 0; ks < 4; ks++) {
            const uint32_t akb = ((uint32_t)(ks * 32) + a_klane) ^ cswz;
            const uint32_t bkb = ((uint32_t)(ks * 32) + b_klane) ^ cswz;
            uint32_t av[2][4];
            LDX4(av[0], sA + a_rowoff + akb);
            LDX4(av[1], sA + a_rowoff + 2048 + akb);
            uint32_t bv[4][4];
            #pragma unroll
            for (int nb = 0; nb < 4; nb++)
                LDX4(bv[nb], sB + b_rowoff + nb * 2048 + bkb);
            #pragma unroll
            for (int ms = 0; ms < 2; ms++) {
                #pragma unroll
                for (int ns = 0; ns < 8; ns++) {
                    const uint32_t* BB = &bv[ns >> 1][(ns & 1) * 2];
                    MMA(acc[ms][ns], av[ms], BB[0], BB[1]);
                }
            }
        }
    }

    // ---- y stores with bias + residual folded in ---------------------------
    const int mrow = mtile * 128 + wm * 32;
    const int ncol = nt * 128 + wn * 64;
    #pragma unroll
    for (int ms = 0; ms < 2; ms++) {
        const int r0 = mrow + ms * 16 + (lane >> 2);
        const int r1 = r0 + 8;
        const float* rp0 = nullptr;
        const float* rp1 = nullptr;
        if (r0 < NROWS) {
            if (res_trans) {
                int g = r0 / N_, n = r0 - g * N_;
                int bb = g / T_, tt = g - bb * T_;
                rp0 = res + ((long)(bb * N_ + n) * T_ + tt) * D_;
            } else rp0 = res + (long)r0 * D_;
        }
        if (r1 < NROWS) {
            if (res_trans) {
                int g = r1 / N_, n = r1 - g * N_;
                int bb = g / T_, tt = g - bb * T_;
                rp1 = res + ((long)(bb * N_ + n) * T_ + tt) * D_;
            } else rp1 = res + (long)r1 * D_;
        }
        #pragma unroll
        for (int ns = 0; ns < 8; ns++) {
            const int c = ncol + ns * 8 + (lane & 3) * 2;
            const int cl = wn * 64 + ns * 8 + (lane & 3) * 2;
            const float b0 = sBias[cl], b1 = sBias[cl + 1];
            if (r0 < NROWS) {
                float2 rv = *(const float2*)(rp0 + c);
                *(float2*)(y + (size_t)r0 * D_ + c) =
                    make_float2(acc[ms][ns][0] + b0 + rv.x, acc[ms][ns][1] + b1 + rv.y);
            }
            if (r1 < NROWS) {
                float2 rv = *(const float2*)(rp1 + c);
                *(float2*)(y + (size_t)r1 * D_ + c) =
                    make_float2(acc[ms][ns][2] + b0 + rv.x, acc[ms][ns][3] + b1 + rv.y);
            }
        }
    }
}

// ---------------- final: LN + exact GELU -> out (y has bias+res) ------------
__global__ __launch_bounds__(256)
void ln_kernel(const float* __restrict__ y,
               float* __restrict__ dst,
               const float* __restrict__ gamma, const float* __restrict__ beta)
{
    int row = blockIdx.x * 8 + (threadIdx.x >> 5);
    int lane = threadIdx.x & 31;
    if (row >= NROWS) return;
    int g = row / N_, n = row - g * N_;
    int bb = g / T_, tt = g - bb * T_;
    long toff = ((long)(bb * N_ + n) * T_ + tt) * D_;

    float* dp = dst + toff;
    const float* yp = y + (long)row * D_;

    float v[16];
    float sum = 0.0f, sq = 0.0f;
    #pragma unroll
    for (int i = 0; i < 4; i++) {
        int c = lane * 4 + i * 128;
        float4 a = *(const float4*)(yp + c);
        v[i*4+0] = a.x; v[i*4+1] = a.y; v[i*4+2] = a.z; v[i*4+3] = a.w;
        sum += a.x + a.y + a.z + a.w;
        sq = fmaf(a.x, a.x, sq); sq = fmaf(a.y, a.y, sq);
        sq = fmaf(a.z, a.z, sq); sq = fmaf(a.w, a.w, sq);
    }
    #pragma unroll
    for (int o = 16; o; o >>= 1) {
        sum += __shfl_xor_sync(0xffffffffu, sum, o);
        sq  += __shfl_xor_sync(0xffffffffu, sq, o);
    }
    float mu = sum * (1.0f / D_);
    float var = sq * (1.0f / D_) - mu * mu;
    float rstd = rsqrtf(var + LN_EPS);
    #pragma unroll
    for (int i = 0; i < 4; i++) {
        int c = lane * 4 + i * 128;
        float4 g4 = *(const float4*)(gamma + c);
        float4 be4 = *(const float4*)(beta + c);
        float o0 = fmaf((v[i*4+0] - mu) * rstd, g4.x, be4.x);
        float o1 = fmaf((v[i*4+1] - mu) * rstd, g4.y, be4.y);
        float o2 = fmaf((v[i*4+2] - mu) * rstd, g4.z, be4.z);
        float o3 = fmaf((v[i*4+3] - mu) * rstd, g4.w, be4.w);
        o0 = 0.5f * o0 * (1.0f + erff(o0 * 0.70710678118654752f));
        o1 = 0.5f * o1 * (1.0f + erff(o1 * 0.70710678118654752f));
        o2 = 0.5f * o2 * (1.0f + erff(o2 * 0.70710678118654752f));
        o3 = 0.5f * o3 * (1.0f + erff(o3 * 0.70710678118654752f));
        *(float4*)(dp + c) = make_float4(o0, o1, o2, o3);
    }
}

// ---------------- launch -----------------------------------------------------
extern "C" void kernel_launch(void* const* d_in, const int* in_sizes, int n_in,
                              void* d_out, int out_size)
{
    const float* features  = (const float*)d_in[0];
    const float* adjacency = (const float*)d_in[1];
    const float* edge_w    = (const float*)d_in[2];
    const float* edge_b    = (const float*)d_in[3];
    const float* W         = (const float*)d_in[4];
    const float* bias      = (const float*)d_in[5];
    const float* gamma     = (const float*)d_in[6];
    const float* beta      = (const float*)d_in[7];
    float* out = (float*)d_out;

    unsigned char *av, *bv;
    float *yv, *state;
    cudaGetSymbolAddress((void**)&av, g_a);
    cudaGetSymbolAddress((void**)&bv, g_b);
    cudaGetSymbolAddress((void**)&yv, g_y);
    cudaGetSymbolAddress((void**)&state, g_state);

    cudaFuncSetAttribute(gemm_kernel, cudaFuncAttributeMaxDynamicSharedMemorySize,
                         GEMM_SMEM_DYN);

    adj_kernel<<<NGRAPH, 128>>>(adjacency, edge_w, edge_b);
    wconv_kernel<<<256, 256>>>(W);

    const size_t bl = (size_t)KCHUNKS * NTILES * BTILE_BYTES;

    // layer 0: gemm folds bias0 + features residual into y
    mix_kernel<<<NGRAPH, 256>>>(features);
    gemm_kernel<<<MTILES * NTILES, 256, GEMM_SMEM_DYN>>>(
        av, bv, yv, features, 1, bias);
    // fused: layer-0 LN/GELU (writes state) + layer-1 mix (writes A tiles)
    lnmix_kernel<<<NGRAPH, 256>>>(yv, gamma, beta);
    // layer 1: gemm folds bias1 + state residual into y
    gemm_kernel<<<MTILES * NTILES, 256, GEMM_SMEM_DYN>>>(
        av, bv + bl, yv, state, 0, bias + D_);
    ln_kernel<<<(NROWS + 7) / 8, 256>>>(yv, out, gamma + D_, beta + D_);
}

// round 12
// speedup vs baseline: 1.2443x; 1.0547x over previous
#include <cuda_runtime.h>
#include <cuda_fp16.h>
#include <math.h>
#include <stdint.h>

#define B_ 8
#define N_ 19
#define T_ 1000
#define D_ 512
#define ALPHA 0.05f
#define LN_EPS 1e-5f
#define ROW_EPS 1e-6f

#define NGRAPH (B_ * T_)       // 8000
#define NROWS (NGRAPH * N_)    // 152000
#define MTILES 1188            // ceil(152000/128)
#define NTILES 4               // 512/128
#define KCHUNKS 8              // 512/64
#define ATILE_BYTES 16384      // 128 rows x 64 k x fp16 (swizzled)
#define BTILE_BYTES 16384      // 128 n   x 64 k x fp16 (swizzled)
#define STAGE_BYTES 32768      // A(16K) + B(16K)
#define NSTAGES 3
#define GEMM_SMEM_DYN (NSTAGES * STAGE_BYTES + 1024)

// ---------------- scratch (__device__ globals; no runtime alloc) ------------
__device__ __align__(16) unsigned char g_a[(size_t)MTILES * KCHUNKS * ATILE_BYTES];
__device__ __align__(16) unsigned char g_b[2 * KCHUNKS * NTILES * BTILE_BYTES];
__device__ float g_adjn[(size_t)NGRAPH * N_ * N_];
__device__ __align__(16) __half g_state[(size_t)NROWS * D_];
__device__ __align__(16) __half g_y[(size_t)MTILES * 128 * D_];

// ---------------- helpers ---------------------------------------------------
__device__ __forceinline__ uint32_t swz(uint32_t o) { return o ^ ((o >> 3) & 0x70); }

__device__ __forceinline__ uint32_t smem_u32(const void* p) {
    uint32_t a;
    asm("{ .reg .u64 t; cvta.to.shared.u64 t, %1; cvt.u32.u64 %0, t; }" : "=r"(a) : "l"(p));
    return a;
}
__device__ __forceinline__ void bulk_g2s(uint32_t dst, const void* src,
                                         uint32_t bytes, uint32_t mbar) {
    asm volatile(
        "cp.async.bulk.shared::cta.global.mbarrier::complete_tx::bytes [%0], [%1], %2, [%3];"
        :: "r"(dst), "l"(src), "r"(bytes), "r"(mbar) : "memory");
}
#define MBAR_INIT(a, c) asm volatile("mbarrier.init.shared.b64 [%0], %1;" :: "r"(a), "r"(c) : "memory")
#define MBAR_EXPECT(a, b) asm volatile("mbarrier.arrive.expect_tx.shared.b64 _, [%0], %1;" :: "r"(a), "r"(b) : "memory")
#define MBAR_WAIT(addr, ph) do {                                                      \
    asm volatile(                                                                     \
        "{\n\t.reg .pred P;\n\t"                                                      \
        "WL_%=:\n\t"                                                                  \
        "mbarrier.try_wait.parity.acquire.cta.shared::cta.b64 P, [%0], %1, 0x989680;\n\t" \
        "@P bra.uni WD_%=;\n\t"                                                       \
        "bra.uni WL_%=;\n\t"                                                          \
        "WD_%=:\n\t}"                                                                 \
        :: "r"(addr), "r"(ph) : "memory");                                            \
} while (0)

#define LDX4(r, a)                                                                    \
    asm volatile("ldmatrix.sync.aligned.m8n8.x4.shared.b16 {%0,%1,%2,%3}, [%4];"      \
        : "=r"((r)[0]), "=r"((r)[1]), "=r"((r)[2]), "=r"((r)[3]) : "r"(a))

#define MMA(c, a, b0v, b1v)                                                           \
    asm volatile("mma.sync.aligned.m16n8k16.row.col.f32.f16.f16.f32 "                 \
        "{%0,%1,%2,%3},{%4,%5,%6,%7},{%8,%9},{%0,%1,%2,%3};"                          \
        : "+f"((c)[0]), "+f"((c)[1]), "+f"((c)[2]), "+f"((c)[3])                      \
        : "r"((a)[0]), "r"((a)[1]), "r"((a)[2]), "r"((a)[3]), "r"(b0v), "r"(b1v))

// load 4 consecutive halfs -> 4 floats
__device__ __forceinline__ void ldh4(const __half* p, float* f) {
    uint2 q = *reinterpret_cast<const uint2*>(p);
    __half2 h0 = *reinterpret_cast<__half2*>(&q.x);
    __half2 h1 = *reinterpret_cast<__half2*>(&q.y);
    float2 a = __half22float2(h0), b = __half22float2(h1);
    f[0] = a.x; f[1] = a.y; f[2] = b.x; f[3] = b.y;
}
__device__ __forceinline__ void sth4(__half* p, float a, float b, float c, float d) {
    uint2 q;
    __half2 h0 = __floats2half2_rn(a, b);
    __half2 h1 = __floats2half2_rn(c, d);
    q.x = *reinterpret_cast<uint32_t*>(&h0);
    q.y = *reinterpret_cast<uint32_t*>(&h1);
    *reinterpret_cast<uint2*>(p) = q;
}

// ---------------- adjacency softplus + row-normalize ------------------------
__global__ __launch_bounds__(128)
void adj_kernel(const float* __restrict__ adjacency,
                const float* __restrict__ edge_w, const float* __restrict__ edge_b)
{
    __shared__ float s[N_][N_];
    int g = blockIdx.x, tid = threadIdx.x;
    float ew = edge_w[0], eb = edge_b[0];
    const float* a = adjacency + (size_t)g * N_ * N_;
    for (int i = tid; i < N_ * N_; i += 128) {
        float v = fmaf(a[i], ew, eb);
        ((float*)s)[i] = fmaxf(v, 0.0f) + log1pf(expf(-fabsf(v)));
    }
    __syncthreads();
    if (tid < N_) {
        float sum = 0.0f;
        #pragma unroll
        for (int j = 0; j < N_; j++) sum += s[tid][j];
        float inv = 1.0f / (sum + ROW_EPS);
        #pragma unroll
        for (int j = 0; j < N_; j++) s[tid][j] *= inv;
    }
    __syncthreads();
    for (int i = tid; i < N_ * N_; i += 128)
        g_adjn[(size_t)g * N_ * N_ + i] = ((float*)s)[i];
}

// ---------------- W -> fp16 W^T tiles (n-major, swizzled) -------------------
__global__ __launch_bounds__(256)
void wconv_kernel(const float* __restrict__ W)
{
    int p = blockIdx.x * 256 + threadIdx.x;
    if (p >= 2 * 512 * 64) return;
    int l = p >> 15;
    int rem = p & 32767;
    int n = rem >> 6;
    int k8 = rem & 63;
    int k0 = k8 * 8;
    const float* src = W + (size_t)l * D_ * D_ + n;
    union { uint4 q; __half h[8]; } H;
    #pragma unroll
    for (int i = 0; i < 8; i++)
        H.h[i] = __float2half_rn(src[(size_t)(k0 + i) * D_]);
    int kchunk = k0 >> 6, nq = n >> 7, nl = n & 127, kl = k0 & 63;
    size_t blk = (size_t)l * (KCHUNKS * NTILES) + kchunk * NTILES + nq;
    uint32_t off = swz((uint32_t)(nl * 128 + kl * 2));
    *(uint4*)(g_b + blk * BTILE_BYTES + off) = H.q;
}

// ---------------- shared mixing routine (operates on xs in smem) ------------
__device__ __forceinline__ void do_mix_split(const float (*xs)[D_],
                                             const float (*sadj)[N_],
                                             int g, int tid)
{
    for (int task = tid; task < N_ * 64; task += 256) {
        int n = task >> 6, k8 = task & 63, d0 = k8 << 3;
        float m[8];
        #pragma unroll
        for (int i = 0; i < 8; i++) m[i] = (1.0f - ALPHA) * xs[n][d0 + i];
        #pragma unroll
        for (int j = 0; j < N_; j++) {
            float a = ALPHA * sadj[n][j];
            #pragma unroll
            for (int i = 0; i < 8; i++) m[i] = fmaf(a, xs[j][d0 + i], m[i]);
        }
        union { uint4 q; __half h[8]; } H;
        #pragma unroll
        for (int i = 0; i < 8; i++) H.h[i] = __float2half_rn(m[i]);
        int r = g * N_ + n;
        int mt = r >> 7, rl = r & 127;
        size_t blk = (size_t)mt * KCHUNKS + (k8 >> 3);
        uint32_t off = swz((uint32_t)(rl * 128 + (k8 & 7) * 16));
        *(uint4*)(g_a + blk * ATILE_BYTES + off) = H.q;
    }
}

// ---------------- layer-0 mix: features -> A tiles ---------------------------
__global__ __launch_bounds__(256)
void mix_kernel(const float* __restrict__ src)
{
    __shared__ float xs[N_][D_];
    __shared__ float sadj[N_][N_];
    int g = blockIdx.x, tid = threadIdx.x;
    for (int i = tid; i < N_ * N_; i += 256)
        ((float*)sadj)[i] = g_adjn[(size_t)g * N_ * N_ + i];
    int bb = g / T_, tt = g - bb * T_;
    long tb = (long)bb * N_ * T_ * D_ + (long)tt * D_;
    for (int idx = tid; idx < N_ * D_; idx += 256) {
        int n = idx >> 9, d = idx & (D_ - 1);
        xs[n][d] = src[tb + (long)n * T_ * D_ + d];
    }
    __syncthreads();
    do_mix_split(xs, sadj, g, tid);
}

// ---------------- fused: layer-0 LN/GELU + layer-1 mix ----------------------
__global__ __launch_bounds__(256)
void lnmix_kernel(const __half* __restrict__ y,
                  const float* __restrict__ features,
                  const float* __restrict__ gamma, const float* __restrict__ beta,
                  const float* __restrict__ bias)
{
    __shared__ float xs[N_][D_];
    __shared__ float sadj[N_][N_];
    int g = blockIdx.x, tid = threadIdx.x;
    int wid = tid >> 5, lane = tid & 31;
    for (int i = tid; i < N_ * N_; i += 256)
        ((float*)sadj)[i] = g_adjn[(size_t)g * N_ * N_ + i];

    int bb = g / T_, tt = g - bb * T_;
    const long tb = (long)bb * N_ * T_ * D_ + (long)tt * D_;

    for (int r = wid; r < N_; r += 8) {
        const long row = (long)g * N_ + r;
        const __half* yp = y + row * D_;
        const float* rp = features + tb + (long)r * T_ * D_;
        float v[16];
        float sum = 0.0f, sq = 0.0f;
        #pragma unroll
        for (int i = 0; i < 4; i++) {
            int c = lane * 4 + i * 128;
            float a[4];
            ldh4(yp + c, a);
            float4 r4 = *(const float4*)(rp + c);
            float4 b4 = *(const float4*)(bias + c);
            float t0 = a[0] + b4.x + r4.x, t1 = a[1] + b4.y + r4.y;
            float t2 = a[2] + b4.z + r4.z, t3 = a[3] + b4.w + r4.w;
            v[i*4+0] = t0; v[i*4+1] = t1; v[i*4+2] = t2; v[i*4+3] = t3;
            sum += t0 + t1 + t2 + t3;
            sq = fmaf(t0, t0, sq); sq = fmaf(t1, t1, sq);
            sq = fmaf(t2, t2, sq); sq = fmaf(t3, t3, sq);
        }
        #pragma unroll
        for (int o = 16; o; o >>= 1) {
            sum += __shfl_xor_sync(0xffffffffu, sum, o);
            sq  += __shfl_xor_sync(0xffffffffu, sq, o);
        }
        float mu = sum * (1.0f / D_);
        float var = sq * (1.0f / D_) - mu * mu;
        float rstd = rsqrtf(var + LN_EPS);
        __half* sp = g_state + row * D_;
        #pragma unroll
        for (int i = 0; i < 4; i++) {
            int c = lane * 4 + i * 128;
            float4 g4 = *(const float4*)(gamma + c);
            float4 be4 = *(const float4*)(beta + c);
            float o0 = fmaf((v[i*4+0] - mu) * rstd, g4.x, be4.x);
            float o1 = fmaf((v[i*4+1] - mu) * rstd, g4.y, be4.y);
            float o2 = fmaf((v[i*4+2] - mu) * rstd, g4.z, be4.z);
            float o3 = fmaf((v[i*4+3] - mu) * rstd, g4.w, be4.w);
            o0 = 0.5f * o0 * (1.0f + erff(o0 * 0.70710678118654752f));
            o1 = 0.5f * o1 * (1.0f + erff(o1 * 0.70710678118654752f));
            o2 = 0.5f * o2 * (1.0f + erff(o2 * 0.70710678118654752f));
            o3 = 0.5f * o3 * (1.0f + erff(o3 * 0.70710678118654752f));
            xs[r][c] = o0; xs[r][c+1] = o1; xs[r][c+2] = o2; xs[r][c+3] = o3;
            sth4(sp + c, o0, o1, o2, o3);
        }
    }
    __syncthreads();
    do_mix_split(xs, sadj, g, tid);
}

// ---------------- GEMM: 128x128 CTA tile, single fp16 term, 2 CTA/SM --------
__global__ __launch_bounds__(256, 2)
void gemm_kernel(const unsigned char* __restrict__ gA,
                 const unsigned char* __restrict__ gB,
                 __half* __restrict__ y)
{
    extern __shared__ unsigned char smraw[];
    __shared__ __align__(8) unsigned long long s_mbar[NSTAGES];

    const int tid = threadIdx.x, wid = tid >> 5, lane = tid & 31;
    const int wm = wid >> 1, wn = wid & 1;
    const int mtile = blockIdx.x >> 2, nt = blockIdx.x & 3;

    const uint32_t base = (smem_u32(smraw) + 1023) & ~1023u;
    uint32_t mb[NSTAGES];
    #pragma unroll
    for (int i = 0; i < NSTAGES; i++) mb[i] = smem_u32(&s_mbar[0]) + 8 * i;
    if (tid == 0)
        for (int i = 0; i < NSTAGES; i++) MBAR_INIT(mb[i], 1);
    __syncthreads();

    const unsigned char* pA = gA + (size_t)mtile * KCHUNKS * ATILE_BYTES;
    const unsigned char* pB = gB + (size_t)nt * BTILE_BYTES;

    const uint32_t a_rowoff = (wm * 32 + (lane & 15)) * 128;
    const uint32_t a_klane = (uint32_t)(lane >> 4) << 4;
    const uint32_t b_rowoff = (wn * 64 + ((lane >> 4) << 3) + (lane & 7)) * 128;
    const uint32_t b_klane = (uint32_t)((lane >> 3) & 1) << 4;
    const uint32_t cswz = (uint32_t)(lane & 7) << 4;

    float acc[2][8][4];
    #pragma unroll
    for (int ms = 0; ms < 2; ms++)
        #pragma unroll
        for (int ns = 0; ns < 8; ns++)
            #pragma unroll
            for (int q = 0; q < 4; q++) acc[ms][ns][q] = 0.0f;

    if (tid == 0) {
        #pragma unroll
        for (int s = 0; s < 2; s++) {
            const uint32_t st = base + s * STAGE_BYTES;
            MBAR_EXPECT(mb[s], (uint32_t)STAGE_BYTES);
            bulk_g2s(st,         pA + (size_t)s * ATILE_BYTES, ATILE_BYTES, mb[s]);
            bulk_g2s(st + 16384, pB + (size_t)s * NTILES * BTILE_BYTES, BTILE_BYTES, mb[s]);
        }
    }

    for (int kc = 0; kc < KCHUNKS; kc++) {
        const int slot = kc % NSTAGES;
        MBAR_WAIT(mb[slot], (kc / NSTAGES) & 1);
        __syncthreads();
        if (tid == 0 && kc + 2 < KCHUNKS) {
            const int kn = kc + 2, sl = kn % NSTAGES;
            const uint32_t st = base + sl * STAGE_BYTES;
            MBAR_EXPECT(mb[sl], (uint32_t)STAGE_BYTES);
            bulk_g2s(st,         pA + (size_t)kn * ATILE_BYTES, ATILE_BYTES, mb[sl]);
            bulk_g2s(st + 16384, pB + (size_t)kn * NTILES * BTILE_BYTES, BTILE_BYTES, mb[sl]);
        }
        const uint32_t st = base + slot * STAGE_BYTES;
        const uint32_t sA = st, sB = st + 16384;

        #pragma unroll
        for (int ks = 0; ks < 4; ks++) {
            const uint32_t akb = ((uint32_t)(ks * 32) + a_klane) ^ cswz;
            const uint32_t bkb = ((uint32_t)(ks * 32) + b_klane) ^ cswz;
            uint32_t av[2][4];
            LDX4(av[0], sA + a_rowoff + akb);
            LDX4(av[1], sA + a_rowoff + 2048 + akb);
            uint32_t bv[4][4];
            #pragma unroll
            for (int nb = 0; nb < 4; nb++)
                LDX4(bv[nb], sB + b_rowoff + nb * 2048 + bkb);
            #pragma unroll
            for (int ms = 0; ms < 2; ms++) {
                #pragma unroll
                for (int ns = 0; ns < 8; ns++) {
                    const uint32_t* BB = &bv[ns >> 1][(ns & 1) * 2];
                    MMA(acc[ms][ns], av[ms], BB[0], BB[1]);
                }
            }
        }
    }

    const int mrow = mtile * 128 + wm * 32;
    const int ncol = nt * 128 + wn * 64;
    #pragma unroll
    for (int ms = 0; ms < 2; ms++) {
        const int r0 = mrow + ms * 16 + (lane >> 2);
        const int r1 = r0 + 8;
        #pragma unroll
        for (int ns = 0; ns < 8; ns++) {
            const int c = ncol + ns * 8 + (lane & 3) * 2;
            if (r0 < NROWS) {
                __half2 h = __floats2half2_rn(acc[ms][ns][0], acc[ms][ns][1]);
                *(__half2*)(y + (size_t)r0 * D_ + c) = h;
            }
            if (r1 < NROWS) {
                __half2 h = __floats2half2_rn(acc[ms][ns][2], acc[ms][ns][3]);
                *(__half2*)(y + (size_t)r1 * D_ + c) = h;
            }
        }
    }
}

// ---------------- final: bias + residual + LN + exact GELU -> out ------------
__global__ __launch_bounds__(256)
void ln_kernel(const __half* __restrict__ y,
               const __half* __restrict__ res,
               float* __restrict__ dst,
               const float* __restrict__ gamma, const float* __restrict__ beta,
               const float* __restrict__ bias)
{
    int row = blockIdx.x * 8 + (threadIdx.x >> 5);
    int lane = threadIdx.x & 31;
    if (row >= NROWS) return;
    int g = row / N_, n = row - g * N_;
    int bb = g / T_, tt = g - bb * T_;
    long toff = ((long)(bb * N_ + n) * T_ + tt) * D_;

    const __half* rp = res + (long)row * D_;
    float* dp = dst + toff;
    const __half* yp = y + (long)row * D_;

    float v[16];
    float sum = 0.0f, sq = 0.0f;
    #pragma unroll
    for (int i = 0; i < 4; i++) {
        int c = lane * 4 + i * 128;
        float a[4], r4[4];
        ldh4(yp + c, a);
        ldh4(rp + c, r4);
        float4 b4 = *(const float4*)(bias + c);
        float t0 = a[0] + b4.x + r4[0], t1 = a[1] + b4.y + r4[1];
        float t2 = a[2] + b4.z + r4[2], t3 = a[3] + b4.w + r4[3];
        v[i*4+0] = t0; v[i*4+1] = t1; v[i*4+2] = t2; v[i*4+3] = t3;
        sum += t0 + t1 + t2 + t3;
        sq = fmaf(t0, t0, sq); sq = fmaf(t1, t1, sq);
        sq = fmaf(t2, t2, sq); sq = fmaf(t3, t3, sq);
    }
    #pragma unroll
    for (int o = 16; o; o >>= 1) {
        sum += __shfl_xor_sync(0xffffffffu, sum, o);
        sq  += __shfl_xor_sync(0xffffffffu, sq, o);
    }
    float mu = sum * (1.0f / D_);
    float var = sq * (1.0f / D_) - mu * mu;
    float rstd = rsqrtf(var + LN_EPS);
    #pragma unroll
    for (int i = 0; i < 4; i++) {
        int c = lane * 4 + i * 128;
        float4 g4 = *(const float4*)(gamma + c);
        float4 be4 = *(const float4*)(beta + c);
        float o0 = fmaf((v[i*4+0] - mu) * rstd, g4.x, be4.x);
        float o1 = fmaf((v[i*4+1] - mu) * rstd, g4.y, be4.y);
        float o2 = fmaf((v[i*4+2] - mu) * rstd, g4.z, be4.z);
        float o3 = fmaf((v[i*4+3] - mu) * rstd, g4.w, be4.w);
        o0 = 0.5f * o0 * (1.0f + erff(o0 * 0.70710678118654752f));
        o1 = 0.5f * o1 * (1.0f + erff(o1 * 0.70710678118654752f));
        o2 = 0.5f * o2 * (1.0f + erff(o2 * 0.70710678118654752f));
        o3 = 0.5f * o3 * (1.0f + erff(o3 * 0.70710678118654752f));
        *(float4*)(dp + c) = make_float4(o0, o1, o2, o3);
    }
}

// ---------------- launch -----------------------------------------------------
extern "C" void kernel_launch(void* const* d_in, const int* in_sizes, int n_in,
                              void* d_out, int out_size)
{
    const float* features  = (const float*)d_in[0];
    const float* adjacency = (const float*)d_in[1];
    const float* edge_w    = (const float*)d_in[2];
    const float* edge_b    = (const float*)d_in[3];
    const float* W         = (const float*)d_in[4];
    const float* bias      = (const float*)d_in[5];
    const float* gamma     = (const float*)d_in[6];
    const float* beta      = (const float*)d_in[7];
    float* out = (float*)d_out;

    unsigned char *av, *bv;
    __half *yv, *state;
    cudaGetSymbolAddress((void**)&av, g_a);
    cudaGetSymbolAddress((void**)&bv, g_b);
    cudaGetSymbolAddress((void**)&yv, g_y);
    cudaGetSymbolAddress((void**)&state, g_state);

    cudaFuncSetAttribute(gemm_kernel, cudaFuncAttributeMaxDynamicSharedMemorySize,
                         GEMM_SMEM_DYN);

    adj_kernel<<<NGRAPH, 128>>>(adjacency, edge_w, edge_b);
    wconv_kernel<<<256, 256>>>(W);

    const size_t bl = (size_t)KCHUNKS * NTILES * BTILE_BYTES;

    // layer 0
    mix_kernel<<<NGRAPH, 256>>>(features);
    gemm_kernel<<<MTILES * NTILES, 256, GEMM_SMEM_DYN>>>(av, bv, yv);
    // fused: layer-0 LN/GELU (writes state fp16) + layer-1 mix (writes A tiles)
    lnmix_kernel<<<NGRAPH, 256>>>(yv, features, gamma, beta, bias);
    // layer 1
    gemm_kernel<<<MTILES * NTILES, 256, GEMM_SMEM_DYN>>>(av, bv + bl, yv);
    ln_kernel<<<(NROWS + 7) / 8, 256>>>(yv, state, out,
                                        gamma + D_, beta + D_, bias + D_);
}

// round 13
// speedup vs baseline: 1.2491x; 1.0038x over previous
#include <cuda_runtime.h>
#include <cuda_fp16.h>
#include <math.h>
#include <stdint.h>

#define B_ 8
#define N_ 19
#define T_ 1000
#define D_ 512
#define ALPHA 0.05f
#define LN_EPS 1e-5f
#define ROW_EPS 1e-6f

#define NGRAPH (B_ * T_)       // 8000
#define NROWS (NGRAPH * N_)    // 152000
#define MTILES 1188
#define NTILES 4
#define KCHUNKS 8
#define ATILE_BYTES 16384
#define BTILE_BYTES 16384
#define STAGE_BYTES 32768
#define NSTAGES 3
#define GEMM_SMEM_DYN (NSTAGES * STAGE_BYTES + 1024)

// chain split: graphs [0,4096) -> mtiles [0,608); graphs [4096,8000) -> [608,1188)
#define G1 4096
#define G2 (NGRAPH - G1)       // 3904
#define MT1 608
#define MT2 (MTILES - MT1)     // 580
#define LNB1 (G1 * N_ / 8)     // 77824/8 = 9728
#define LNB2 ((NROWS - G1 * N_ + 7) / 8)  // 9272

// ---------------- scratch ----------------------------------------------------
__device__ __align__(16) unsigned char g_a[(size_t)MTILES * KCHUNKS * ATILE_BYTES];
__device__ __align__(16) unsigned char g_b[2 * KCHUNKS * NTILES * BTILE_BYTES];
__device__ float g_adjn[(size_t)NGRAPH * N_ * N_];
__device__ __align__(16) __half g_state[(size_t)NROWS * D_];
__device__ __align__(16) __half g_y[(size_t)MTILES * 128 * D_];

// ---------------- helpers ---------------------------------------------------
__device__ __forceinline__ uint32_t swz(uint32_t o) { return o ^ ((o >> 3) & 0x70); }

__device__ __forceinline__ uint32_t smem_u32(const void* p) {
    uint32_t a;
    asm("{ .reg .u64 t; cvta.to.shared.u64 t, %1; cvt.u32.u64 %0, t; }" : "=r"(a) : "l"(p));
    return a;
}
__device__ __forceinline__ void bulk_g2s(uint32_t dst, const void* src,
                                         uint32_t bytes, uint32_t mbar) {
    asm volatile(
        "cp.async.bulk.shared::cta.global.mbarrier::complete_tx::bytes [%0], [%1], %2, [%3];"
        :: "r"(dst), "l"(src), "r"(bytes), "r"(mbar) : "memory");
}
#define MBAR_INIT(a, c) asm volatile("mbarrier.init.shared.b64 [%0], %1;" :: "r"(a), "r"(c) : "memory")
#define MBAR_EXPECT(a, b) asm volatile("mbarrier.arrive.expect_tx.shared.b64 _, [%0], %1;" :: "r"(a), "r"(b) : "memory")
#define MBAR_WAIT(addr, ph) do {                                                      \
    asm volatile(                                                                     \
        "{\n\t.reg .pred P;\n\t"                                                      \
        "WL_%=:\n\t"                                                                  \
        "mbarrier.try_wait.parity.acquire.cta.shared::cta.b64 P, [%0], %1, 0x989680;\n\t" \
        "@P bra.uni WD_%=;\n\t"                                                       \
        "bra.uni WL_%=;\n\t"                                                          \
        "WD_%=:\n\t}"                                                                 \
        :: "r"(addr), "r"(ph) : "memory");                                            \
} while (0)

#define LDX4(r, a)                                                                    \
    asm volatile("ldmatrix.sync.aligned.m8n8.x4.shared.b16 {%0,%1,%2,%3}, [%4];"      \
        : "=r"((r)[0]), "=r"((r)[1]), "=r"((r)[2]), "=r"((r)[3]) : "r"(a))

#define MMA(c, a, b0v, b1v)                                                           \
    asm volatile("mma.sync.aligned.m16n8k16.row.col.f32.f16.f16.f32 "                 \
        "{%0,%1,%2,%3},{%4,%5,%6,%7},{%8,%9},{%0,%1,%2,%3};"                          \
        : "+f"((c)[0]), "+f"((c)[1]), "+f"((c)[2]), "+f"((c)[3])                      \
        : "r"((a)[0]), "r"((a)[1]), "r"((a)[2]), "r"((a)[3]), "r"(b0v), "r"(b1v))

__device__ __forceinline__ void ldh4(const __half* p, float* f) {
    uint2 q = *reinterpret_cast<const uint2*>(p);
    __half2 h0 = *reinterpret_cast<__half2*>(&q.x);
    __half2 h1 = *reinterpret_cast<__half2*>(&q.y);
    float2 a = __half22float2(h0), b = __half22float2(h1);
    f[0] = a.x; f[1] = a.y; f[2] = b.x; f[3] = b.y;
}
__device__ __forceinline__ void sth4(__half* p, float a, float b, float c, float d) {
    uint2 q;
    __half2 h0 = __floats2half2_rn(a, b);
    __half2 h1 = __floats2half2_rn(c, d);
    q.x = *reinterpret_cast<uint32_t*>(&h0);
    q.y = *reinterpret_cast<uint32_t*>(&h1);
    *reinterpret_cast<uint2*>(p) = q;
}

// ---------------- adjacency softplus + row-normalize ------------------------
__global__ __launch_bounds__(128)
void adj_kernel(const float* __restrict__ adjacency,
                const float* __restrict__ edge_w, const float* __restrict__ edge_b,
                int g0)
{
    __shared__ float s[N_][N_];
    int g = blockIdx.x + g0, tid = threadIdx.x;
    float ew = edge_w[0], eb = edge_b[0];
    const float* a = adjacency + (size_t)g * N_ * N_;
    for (int i = tid; i < N_ * N_; i += 128) {
        float v = fmaf(a[i], ew, eb);
        ((float*)s)[i] = fmaxf(v, 0.0f) + log1pf(expf(-fabsf(v)));
    }
    __syncthreads();
    if (tid < N_) {
        float sum = 0.0f;
        #pragma unroll
        for (int j = 0; j < N_; j++) sum += s[tid][j];
        float inv = 1.0f / (sum + ROW_EPS);
        #pragma unroll
        for (int j = 0; j < N_; j++) s[tid][j] *= inv;
    }
    __syncthreads();
    for (int i = tid; i < N_ * N_; i += 128)
        g_adjn[(size_t)g * N_ * N_ + i] = ((float*)s)[i];
}

// ---------------- W -> fp16 W^T tiles (n-major, swizzled) -------------------
__global__ __launch_bounds__(256)
void wconv_kernel(const float* __restrict__ W)
{
    int p = blockIdx.x * 256 + threadIdx.x;
    if (p >= 2 * 512 * 64) return;
    int l = p >> 15;
    int rem = p & 32767;
    int n = rem >> 6;
    int k8 = rem & 63;
    int k0 = k8 * 8;
    const float* src = W + (size_t)l * D_ * D_ + n;
    union { uint4 q; __half h[8]; } H;
    #pragma unroll
    for (int i = 0; i < 8; i++)
        H.h[i] = __float2half_rn(src[(size_t)(k0 + i) * D_]);
    int kchunk = k0 >> 6, nq = n >> 7, nl = n & 127, kl = k0 & 63;
    size_t blk = (size_t)l * (KCHUNKS * NTILES) + kchunk * NTILES + nq;
    uint32_t off = swz((uint32_t)(nl * 128 + kl * 2));
    *(uint4*)(g_b + blk * BTILE_BYTES + off) = H.q;
}

// ---------------- shared mixing routine -------------------------------------
__device__ __forceinline__ void do_mix_split(const float (*xs)[D_],
                                             const float (*sadj)[N_],
                                             int g, int tid)
{
    for (int task = tid; task < N_ * 64; task += 256) {
        int n = task >> 6, k8 = task & 63, d0 = k8 << 3;
        float m[8];
        #pragma unroll
        for (int i = 0; i < 8; i++) m[i] = (1.0f - ALPHA) * xs[n][d0 + i];
        #pragma unroll
        for (int j = 0; j < N_; j++) {
            float a = ALPHA * sadj[n][j];
            #pragma unroll
            for (int i = 0; i < 8; i++) m[i] = fmaf(a, xs[j][d0 + i], m[i]);
        }
        union { uint4 q; __half h[8]; } H;
        #pragma unroll
        for (int i = 0; i < 8; i++) H.h[i] = __float2half_rn(m[i]);
        int r = g * N_ + n;
        int mt = r >> 7, rl = r & 127;
        size_t blk = (size_t)mt * KCHUNKS + (k8 >> 3);
        uint32_t off = swz((uint32_t)(rl * 128 + (k8 & 7) * 16));
        *(uint4*)(g_a + blk * ATILE_BYTES + off) = H.q;
    }
}

// ---------------- layer-0 mix ------------------------------------------------
__global__ __launch_bounds__(256)
void mix_kernel(const float* __restrict__ src, int g0)
{
    __shared__ float xs[N_][D_];
    __shared__ float sadj[N_][N_];
    int g = blockIdx.x + g0, tid = threadIdx.x;
    for (int i = tid; i < N_ * N_; i += 256)
        ((float*)sadj)[i] = g_adjn[(size_t)g * N_ * N_ + i];
    int bb = g / T_, tt = g - bb * T_;
    long tb = (long)bb * N_ * T_ * D_ + (long)tt * D_;
    for (int idx = tid; idx < N_ * D_; idx += 256) {
        int n = idx >> 9, d = idx & (D_ - 1);
        xs[n][d] = src[tb + (long)n * T_ * D_ + d];
    }
    __syncthreads();
    do_mix_split(xs, sadj, g, tid);
}

// ---------------- fused: layer-0 LN/GELU + layer-1 mix ----------------------
__global__ __launch_bounds__(256)
void lnmix_kernel(const __half* __restrict__ y,
                  const float* __restrict__ features,
                  const float* __restrict__ gamma, const float* __restrict__ beta,
                  const float* __restrict__ bias, int g0)
{
    __shared__ float xs[N_][D_];
    __shared__ float sadj[N_][N_];
    int g = blockIdx.x + g0, tid = threadIdx.x;
    int wid = tid >> 5, lane = tid & 31;
    for (int i = tid; i < N_ * N_; i += 256)
        ((float*)sadj)[i] = g_adjn[(size_t)g * N_ * N_ + i];

    int bb = g / T_, tt = g - bb * T_;
    const long tb = (long)bb * N_ * T_ * D_ + (long)tt * D_;

    for (int r = wid; r < N_; r += 8) {
        const long row = (long)g * N_ + r;
        const __half* yp = y + row * D_;
        const float* rp = features + tb + (long)r * T_ * D_;
        float v[16];
        float sum = 0.0f, sq = 0.0f;
        #pragma unroll
        for (int i = 0; i < 4; i++) {
            int c = lane * 4 + i * 128;
            float a[4];
            ldh4(yp + c, a);
            float4 r4 = *(const float4*)(rp + c);
            float4 b4 = *(const float4*)(bias + c);
            float t0 = a[0] + b4.x + r4.x, t1 = a[1] + b4.y + r4.y;
            float t2 = a[2] + b4.z + r4.z, t3 = a[3] + b4.w + r4.w;
            v[i*4+0] = t0; v[i*4+1] = t1; v[i*4+2] = t2; v[i*4+3] = t3;
            sum += t0 + t1 + t2 + t3;
            sq = fmaf(t0, t0, sq); sq = fmaf(t1, t1, sq);
            sq = fmaf(t2, t2, sq); sq = fmaf(t3, t3, sq);
        }
        #pragma unroll
        for (int o = 16; o; o >>= 1) {
            sum += __shfl_xor_sync(0xffffffffu, sum, o);
            sq  += __shfl_xor_sync(0xffffffffu, sq, o);
        }
        float mu = sum * (1.0f / D_);
        float var = sq * (1.0f / D_) - mu * mu;
        float rstd = rsqrtf(var + LN_EPS);
        __half* sp = g_state + row * D_;
        #pragma unroll
        for (int i = 0; i < 4; i++) {
            int c = lane * 4 + i * 128;
            float4 g4 = *(const float4*)(gamma + c);
            float4 be4 = *(const float4*)(beta + c);
            float o0 = fmaf((v[i*4+0] - mu) * rstd, g4.x, be4.x);
            float o1 = fmaf((v[i*4+1] - mu) * rstd, g4.y, be4.y);
            float o2 = fmaf((v[i*4+2] - mu) * rstd, g4.z, be4.z);
            float o3 = fmaf((v[i*4+3] - mu) * rstd, g4.w, be4.w);
            o0 = 0.5f * o0 * (1.0f + erff(o0 * 0.70710678118654752f));
            o1 = 0.5f * o1 * (1.0f + erff(o1 * 0.70710678118654752f));
            o2 = 0.5f * o2 * (1.0f + erff(o2 * 0.70710678118654752f));
            o3 = 0.5f * o3 * (1.0f + erff(o3 * 0.70710678118654752f));
            xs[r][c] = o0; xs[r][c+1] = o1; xs[r][c+2] = o2; xs[r][c+3] = o3;
            sth4(sp + c, o0, o1, o2, o3);
        }
    }
    __syncthreads();
    do_mix_split(xs, sadj, g, tid);
}

// ---------------- GEMM: 128x128, single fp16 term, 2 CTA/SM -----------------
__global__ __launch_bounds__(256, 2)
void gemm_kernel(const unsigned char* __restrict__ gA,
                 const unsigned char* __restrict__ gB,
                 __half* __restrict__ y, int mt0)
{
    extern __shared__ unsigned char smraw[];
    __shared__ __align__(8) unsigned long long s_mbar[NSTAGES];

    const int tid = threadIdx.x, wid = tid >> 5, lane = tid & 31;
    const int wm = wid >> 1, wn = wid & 1;
    const int mtile = (blockIdx.x >> 2) + mt0, nt = blockIdx.x & 3;

    const uint32_t base = (smem_u32(smraw) + 1023) & ~1023u;
    uint32_t mb[NSTAGES];
    #pragma unroll
    for (int i = 0; i < NSTAGES; i++) mb[i] = smem_u32(&s_mbar[0]) + 8 * i;
    if (tid == 0)
        for (int i = 0; i < NSTAGES; i++) MBAR_INIT(mb[i], 1);
    __syncthreads();

    const unsigned char* pA = gA + (size_t)mtile * KCHUNKS * ATILE_BYTES;
    const unsigned char* pB = gB + (size_t)nt * BTILE_BYTES;

    const uint32_t a_rowoff = (wm * 32 + (lane & 15)) * 128;
    const uint32_t a_klane = (uint32_t)(lane >> 4) << 4;
    const uint32_t b_rowoff = (wn * 64 + ((lane >> 4) << 3) + (lane & 7)) * 128;
    const uint32_t b_klane = (uint32_t)((lane >> 3) & 1) << 4;
    const uint32_t cswz = (uint32_t)(lane & 7) << 4;

    float acc[2][8][4];
    #pragma unroll
    for (int ms = 0; ms < 2; ms++)
        #pragma unroll
        for (int ns = 0; ns < 8; ns++)
            #pragma unroll
            for (int q = 0; q < 4; q++) acc[ms][ns][q] = 0.0f;

    if (tid == 0) {
        #pragma unroll
        for (int s = 0; s < 2; s++) {
            const uint32_t st = base + s * STAGE_BYTES;
            MBAR_EXPECT(mb[s], (uint32_t)STAGE_BYTES);
            bulk_g2s(st,         pA + (size_t)s * ATILE_BYTES, ATILE_BYTES, mb[s]);
            bulk_g2s(st + 16384, pB + (size_t)s * NTILES * BTILE_BYTES, BTILE_BYTES, mb[s]);
        }
    }

    for (int kc = 0; kc < KCHUNKS; kc++) {
        const int slot = kc % NSTAGES;
        MBAR_WAIT(mb[slot], (kc / NSTAGES) & 1);
        __syncthreads();
        if (tid == 0 && kc + 2 < KCHUNKS) {
            const int kn = kc + 2, sl = kn % NSTAGES;
            const uint32_t st = base + sl * STAGE_BYTES;
            MBAR_EXPECT(mb[sl], (uint32_t)STAGE_BYTES);
            bulk_g2s(st,         pA + (size_t)kn * ATILE_BYTES, ATILE_BYTES, mb[sl]);
            bulk_g2s(st + 16384, pB + (size_t)kn * NTILES * BTILE_BYTES, BTILE_BYTES, mb[sl]);
        }
        const uint32_t st = base + slot * STAGE_BYTES;
        const uint32_t sA = st, sB = st + 16384;

        #pragma unroll
        for (int ks = 0; ks < 4; ks++) {
            const uint32_t akb = ((uint32_t)(ks * 32) + a_klane) ^ cswz;
            const uint32_t bkb = ((uint32_t)(ks * 32) + b_klane) ^ cswz;
            uint32_t av[2][4];
            LDX4(av[0], sA + a_rowoff + akb);
            LDX4(av[1], sA + a_rowoff + 2048 + akb);
            uint32_t bv[4][4];
            #pragma unroll
            for (int nb = 0; nb < 4; nb++)
                LDX4(bv[nb], sB + b_rowoff + nb * 2048 + bkb);
            #pragma unroll
            for (int ms = 0; ms < 2; ms++) {
                #pragma unroll
                for (int ns = 0; ns < 8; ns++) {
                    const uint32_t* BB = &bv[ns >> 1][(ns & 1) * 2];
                    MMA(acc[ms][ns], av[ms], BB[0], BB[1]);
                }
            }
        }
    }

    const int mrow = mtile * 128 + wm * 32;
    const int ncol = nt * 128 + wn * 64;
    #pragma unroll
    for (int ms = 0; ms < 2; ms++) {
        const int r0 = mrow + ms * 16 + (lane >> 2);
        const int r1 = r0 + 8;
        #pragma unroll
        for (int ns = 0; ns < 8; ns++) {
            const int c = ncol + ns * 8 + (lane & 3) * 2;
            if (r0 < NROWS) {
                __half2 h = __floats2half2_rn(acc[ms][ns][0], acc[ms][ns][1]);
                *(__half2*)(y + (size_t)r0 * D_ + c) = h;
            }
            if (r1 < NROWS) {
                __half2 h = __floats2half2_rn(acc[ms][ns][2], acc[ms][ns][3]);
                *(__half2*)(y + (size_t)r1 * D_ + c) = h;
            }
        }
    }
}

// ---------------- final: bias + residual + LN + exact GELU -> out ------------
__global__ __launch_bounds__(256)
void ln_kernel(const __half* __restrict__ y,
               const __half* __restrict__ res,
               float* __restrict__ dst,
               const float* __restrict__ gamma, const float* __restrict__ beta,
               const float* __restrict__ bias, int blk0)
{
    int row = (blockIdx.x + blk0) * 8 + (threadIdx.x >> 5);
    int lane = threadIdx.x & 31;
    if (row >= NROWS) return;
    int g = row / N_, n = row - g * N_;
    int bb = g / T_, tt = g - bb * T_;
    long toff = ((long)(bb * N_ + n) * T_ + tt) * D_;

    const __half* rp = res + (long)row * D_;
    float* dp = dst + toff;
    const __half* yp = y + (long)row * D_;

    float v[16];
    float sum = 0.0f, sq = 0.0f;
    #pragma unroll
    for (int i = 0; i < 4; i++) {
        int c = lane * 4 + i * 128;
        float a[4], r4[4];
        ldh4(yp + c, a);
        ldh4(rp + c, r4);
        float4 b4 = *(const float4*)(bias + c);
        float t0 = a[0] + b4.x + r4[0], t1 = a[1] + b4.y + r4[1];
        float t2 = a[2] + b4.z + r4[2], t3 = a[3] + b4.w + r4[3];
        v[i*4+0] = t0; v[i*4+1] = t1; v[i*4+2] = t2; v[i*4+3] = t3;
        sum += t0 + t1 + t2 + t3;
        sq = fmaf(t0, t0, sq); sq = fmaf(t1, t1, sq);
        sq = fmaf(t2, t2, sq); sq = fmaf(t3, t3, sq);
    }
    #pragma unroll
    for (int o = 16; o; o >>= 1) {
        sum += __shfl_xor_sync(0xffffffffu, sum, o);
        sq  += __shfl_xor_sync(0xffffffffu, sq, o);
    }
    float mu = sum * (1.0f / D_);
    float var = sq * (1.0f / D_) - mu * mu;
    float rstd = rsqrtf(var + LN_EPS);
    #pragma unroll
    for (int i = 0; i < 4; i++) {
        int c = lane * 4 + i * 128;
        float4 g4 = *(const float4*)(gamma + c);
        float4 be4 = *(const float4*)(beta + c);
        float o0 = fmaf((v[i*4+0] - mu) * rstd, g4.x, be4.x);
        float o1 = fmaf((v[i*4+1] - mu) * rstd, g4.y, be4.y);
        float o2 = fmaf((v[i*4+2] - mu) * rstd, g4.z, be4.z);
        float o3 = fmaf((v[i*4+3] - mu) * rstd, g4.w, be4.w);
        o0 = 0.5f * o0 * (1.0f + erff(o0 * 0.70710678118654752f));
        o1 = 0.5f * o1 * (1.0f + erff(o1 * 0.70710678118654752f));
        o2 = 0.5f * o2 * (1.0f + erff(o2 * 0.70710678118654752f));
        o3 = 0.5f * o3 * (1.0f + erff(o3 * 0.70710678118654752f));
        *(float4*)(dp + c) = make_float4(o0, o1, o2, o3);
    }
}

// ---------------- streams/events (created at load time, reused forever) -----
struct GcmStreams {
    cudaStream_t s1, s2;
    cudaEvent_t e_root, e_w, e1, e2;
    GcmStreams() {
        cudaStreamCreateWithFlags(&s1, cudaStreamNonBlocking);
        cudaStreamCreateWithFlags(&s2, cudaStreamNonBlocking);
        cudaEventCreateWithFlags(&e_root, cudaEventDisableTiming);
        cudaEventCreateWithFlags(&e_w, cudaEventDisableTiming);
        cudaEventCreateWithFlags(&e1, cudaEventDisableTiming);
        cudaEventCreateWithFlags(&e2, cudaEventDisableTiming);
    }
};
static GcmStreams g_str;

// ---------------- launch -----------------------------------------------------
extern "C" void kernel_launch(void* const* d_in, const int* in_sizes, int n_in,
                              void* d_out, int out_size)
{
    const float* features  = (const float*)d_in[0];
    const float* adjacency = (const float*)d_in[1];
    const float* edge_w    = (const float*)d_in[2];
    const float* edge_b    = (const float*)d_in[3];
    const float* W         = (const float*)d_in[4];
    const float* bias      = (const float*)d_in[5];
    const float* gamma     = (const float*)d_in[6];
    const float* beta      = (const float*)d_in[7];
    float* out = (float*)d_out;

    unsigned char *av, *bv;
    __half *yv, *state;
    cudaGetSymbolAddress((void**)&av, g_a);
    cudaGetSymbolAddress((void**)&bv, g_b);
    cudaGetSymbolAddress((void**)&yv, g_y);
    cudaGetSymbolAddress((void**)&state, g_state);

    cudaFuncSetAttribute(gemm_kernel, cudaFuncAttributeMaxDynamicSharedMemorySize,
                         GEMM_SMEM_DYN);

    const size_t bl = (size_t)KCHUNKS * NTILES * BTILE_BYTES;
    cudaStream_t s1 = g_str.s1, s2 = g_str.s2;

    // fork from capture/origin stream
    cudaEventRecord(g_str.e_root, 0);
    cudaStreamWaitEvent(s1, g_str.e_root, 0);
    cudaStreamWaitEvent(s2, g_str.e_root, 0);

    // ---- chain X (graphs [0,4096), mtiles [0,608)) on s1 --------------------
    wconv_kernel<<<256, 256, 0, s1>>>(W);
    cudaEventRecord(g_str.e_w, s1);          // B tiles ready
    adj_kernel<<<G1, 128, 0, s1>>>(adjacency, edge_w, edge_b, 0);
    mix_kernel<<<G1, 256, 0, s1>>>(features, 0);
    gemm_kernel<<<MT1 * NTILES, 256, GEMM_SMEM_DYN, s1>>>(av, bv, yv, 0);
    lnmix_kernel<<<G1, 256, 0, s1>>>(yv, features, gamma, beta, bias, 0);
    gemm_kernel<<<MT1 * NTILES, 256, GEMM_SMEM_DYN, s1>>>(av, bv + bl, yv, 0);
    ln_kernel<<<LNB1, 256, 0, s1>>>(yv, state, out, gamma + D_, beta + D_,
                                    bias + D_, 0);
    cudaEventRecord(g_str.e1, s1);

    // ---- chain Y (graphs [4096,8000), mtiles [608,1188)) on s2 --------------
    adj_kernel<<<G2, 128, 0, s2>>>(adjacency, edge_w, edge_b, G1);
    mix_kernel<<<G2, 256, 0, s2>>>(features, G1);
    cudaStreamWaitEvent(s2, g_str.e_w, 0);   // needs B tiles
    gemm_kernel<<<MT2 * NTILES, 256, GEMM_SMEM_DYN, s2>>>(av, bv, yv, MT1);
    lnmix_kernel<<<G2, 256, 0, s2>>>(yv, features, gamma, beta, bias, G1);
    gemm_kernel<<<MT2 * NTILES, 256, GEMM_SMEM_DYN, s2>>>(av, bv + bl, yv, MT1);
    ln_kernel<<<LNB2, 256, 0, s2>>>(yv, state, out, gamma + D_, beta + D_,
                                    bias + D_, LNB1);
    cudaEventRecord(g_str.e2, s2);

    // join back to origin stream
    cudaStreamWaitEvent(0, g_str.e1, 0);
    cudaStreamWaitEvent(0, g_str.e2, 0);
}

// round 14
// speedup vs baseline: 1.5604x; 1.2492x over previous
#include <cuda_runtime.h>
#include <cuda_fp16.h>
#include <math.h>
#include <stdint.h>

#define B_ 8
#define N_ 19
#define T_ 1000
#define D_ 512
#define ALPHA 0.05f
#define LN_EPS 1e-5f
#define ROW_EPS 1e-6f

#define NGRAPH (B_ * T_)       // 8000
#define NROWS (NGRAPH * N_)    // 152000
#define MTILES 1188
#define NTILES 4
#define KCHUNKS 8
#define ATILE_BYTES 16384
#define BTILE_BYTES 16384
#define STAGE_BYTES 32768
#define NSTAGES 3
#define GEMM_SMEM_DYN (NSTAGES * STAGE_BYTES + 1024)

// chain split (kept from R12; harmless)
#define G1 4096
#define G2 (NGRAPH - G1)
#define MT1 608
#define MT2 (MTILES - MT1)
#define LNB1 (G1 * N_ / 8)
#define LNB2 ((NROWS - G1 * N_ + 7) / 8)

// ---------------- scratch ----------------------------------------------------
__device__ __align__(16) unsigned char g_a[(size_t)MTILES * KCHUNKS * ATILE_BYTES];
__device__ __align__(16) unsigned char g_b[2 * KCHUNKS * NTILES * BTILE_BYTES];
__device__ float g_adjn[(size_t)NGRAPH * N_ * N_];
__device__ __align__(16) __half g_state[(size_t)NROWS * D_];
__device__ __align__(16) __half g_y[(size_t)MTILES * 128 * D_];

// ---------------- helpers ---------------------------------------------------
__device__ __forceinline__ uint32_t swz(uint32_t o) { return o ^ ((o >> 3) & 0x70); }

__device__ __forceinline__ uint32_t smem_u32(const void* p) {
    uint32_t a;
    asm("{ .reg .u64 t; cvta.to.shared.u64 t, %1; cvt.u32.u64 %0, t; }" : "=r"(a) : "l"(p));
    return a;
}
__device__ __forceinline__ void bulk_g2s(uint32_t dst, const void* src,
                                         uint32_t bytes, uint32_t mbar) {
    asm volatile(
        "cp.async.bulk.shared::cta.global.mbarrier::complete_tx::bytes [%0], [%1], %2, [%3];"
        :: "r"(dst), "l"(src), "r"(bytes), "r"(mbar) : "memory");
}
#define MBAR_INIT(a, c) asm volatile("mbarrier.init.shared.b64 [%0], %1;" :: "r"(a), "r"(c) : "memory")
#define MBAR_EXPECT(a, b) asm volatile("mbarrier.arrive.expect_tx.shared.b64 _, [%0], %1;" :: "r"(a), "r"(b) : "memory")
#define MBAR_WAIT(addr, ph) do {                                                      \
    asm volatile(                                                                     \
        "{\n\t.reg .pred P;\n\t"                                                      \
        "WL_%=:\n\t"                                                                  \
        "mbarrier.try_wait.parity.acquire.cta.shared::cta.b64 P, [%0], %1, 0x989680;\n\t" \
        "@P bra.uni WD_%=;\n\t"                                                       \
        "bra.uni WL_%=;\n\t"                                                          \
        "WD_%=:\n\t}"                                                                 \
        :: "r"(addr), "r"(ph) : "memory");                                            \
} while (0)

#define LDX4(r, a)                                                                    \
    asm volatile("ldmatrix.sync.aligned.m8n8.x4.shared.b16 {%0,%1,%2,%3}, [%4];"      \
        : "=r"((r)[0]), "=r"((r)[1]), "=r"((r)[2]), "=r"((r)[3]) : "r"(a))

#define MMA(c, a, b0v, b1v)                                                           \
    asm volatile("mma.sync.aligned.m16n8k16.row.col.f32.f16.f16.f32 "                 \
        "{%0,%1,%2,%3},{%4,%5,%6,%7},{%8,%9},{%0,%1,%2,%3};"                          \
        : "+f"((c)[0]), "+f"((c)[1]), "+f"((c)[2]), "+f"((c)[3])                      \
        : "r"((a)[0]), "r"((a)[1]), "r"((a)[2]), "r"((a)[3]), "r"(b0v), "r"(b1v))

__device__ __forceinline__ void ldh4(const __half* p, float* f) {
    uint2 q = *reinterpret_cast<const uint2*>(p);
    __half2 h0 = *reinterpret_cast<__half2*>(&q.x);
    __half2 h1 = *reinterpret_cast<__half2*>(&q.y);
    float2 a = __half22float2(h0), b = __half22float2(h1);
    f[0] = a.x; f[1] = a.y; f[2] = b.x; f[3] = b.y;
}
__device__ __forceinline__ void sth4(__half* p, float a, float b, float c, float d) {
    uint2 q;
    __half2 h0 = __floats2half2_rn(a, b);
    __half2 h1 = __floats2half2_rn(c, d);
    q.x = *reinterpret_cast<uint32_t*>(&h0);
    q.y = *reinterpret_cast<uint32_t*>(&h1);
    *reinterpret_cast<uint2*>(p) = q;
}
// unpack 8 halfs (uint4) -> 8 floats
__device__ __forceinline__ void h8tof(uint4 q, float* f) {
    __half2 h0 = *reinterpret_cast<__half2*>(&q.x);
    __half2 h1 = *reinterpret_cast<__half2*>(&q.y);
    __half2 h2 = *reinterpret_cast<__half2*>(&q.z);
    __half2 h3 = *reinterpret_cast<__half2*>(&q.w);
    float2 a = __half22float2(h0), b = __half22float2(h1);
    float2 c = __half22float2(h2), d = __half22float2(h3);
    f[0] = a.x; f[1] = a.y; f[2] = b.x; f[3] = b.y;
    f[4] = c.x; f[5] = c.y; f[6] = d.x; f[7] = d.y;
}

// ---------------- adjacency softplus + row-normalize ------------------------
__global__ __launch_bounds__(128)
void adj_kernel(const float* __restrict__ adjacency,
                const float* __restrict__ edge_w, const float* __restrict__ edge_b,
                int g0)
{
    __shared__ float s[N_][N_];
    int g = blockIdx.x + g0, tid = threadIdx.x;
    float ew = edge_w[0], eb = edge_b[0];
    const float* a = adjacency + (size_t)g * N_ * N_;
    for (int i = tid; i < N_ * N_; i += 128) {
        float v = fmaf(a[i], ew, eb);
        ((float*)s)[i] = fmaxf(v, 0.0f) + log1pf(expf(-fabsf(v)));
    }
    __syncthreads();
    if (tid < N_) {
        float sum = 0.0f;
        #pragma unroll
        for (int j = 0; j < N_; j++) sum += s[tid][j];
        float inv = 1.0f / (sum + ROW_EPS);
        #pragma unroll
        for (int j = 0; j < N_; j++) s[tid][j] *= inv;
    }
    __syncthreads();
    for (int i = tid; i < N_ * N_; i += 128)
        g_adjn[(size_t)g * N_ * N_ + i] = ((float*)s)[i];
}

// ---------------- W -> fp16 W^T tiles ----------------------------------------
__global__ __launch_bounds__(256)
void wconv_kernel(const float* __restrict__ W)
{
    int p = blockIdx.x * 256 + threadIdx.x;
    if (p >= 2 * 512 * 64) return;
    int l = p >> 15;
    int rem = p & 32767;
    int n = rem >> 6;
    int k8 = rem & 63;
    int k0 = k8 * 8;
    const float* src = W + (size_t)l * D_ * D_ + n;
    union { uint4 q; __half h[8]; } H;
    #pragma unroll
    for (int i = 0; i < 8; i++)
        H.h[i] = __float2half_rn(src[(size_t)(k0 + i) * D_]);
    int kchunk = k0 >> 6, nq = n >> 7, nl = n & 127, kl = k0 & 63;
    size_t blk = (size_t)l * (KCHUNKS * NTILES) + kchunk * NTILES + nq;
    uint32_t off = swz((uint32_t)(nl * 128 + kl * 2));
    *(uint4*)(g_b + blk * BTILE_BYTES + off) = H.q;
}

// ---------------- shared mixing routine (xs in fp16, conflict-free LDS.128) --
__device__ __forceinline__ void do_mix_split(const __half (*xs)[D_],
                                             const float (*sadj)[N_],
                                             int g, int tid)
{
    for (int task = tid; task < N_ * 64; task += 256) {
        int n = task >> 6, k8 = task & 63, d0 = k8 << 3;
        float m[8];
        {
            float self[8];
            h8tof(*reinterpret_cast<const uint4*>(&xs[n][d0]), self);
            #pragma unroll
            for (int i = 0; i < 8; i++) m[i] = (1.0f - ALPHA) * self[i];
        }
        #pragma unroll
        for (int j = 0; j < N_; j++) {
            float a = ALPHA * sadj[n][j];
            float xj[8];
            h8tof(*reinterpret_cast<const uint4*>(&xs[j][d0]), xj);
            #pragma unroll
            for (int i = 0; i < 8; i++) m[i] = fmaf(a, xj[i], m[i]);
        }
        union { uint4 q; __half h[8]; } H;
        #pragma unroll
        for (int i = 0; i < 8; i++) H.h[i] = __float2half_rn(m[i]);
        int r = g * N_ + n;
        int mt = r >> 7, rl = r & 127;
        size_t blk = (size_t)mt * KCHUNKS + (k8 >> 3);
        uint32_t off = swz((uint32_t)(rl * 128 + (k8 & 7) * 16));
        *(uint4*)(g_a + blk * ATILE_BYTES + off) = H.q;
    }
}

// ---------------- layer-0 mix ------------------------------------------------
__global__ __launch_bounds__(256)
void mix_kernel(const float* __restrict__ src, int g0)
{
    __shared__ __half xs[N_][D_];        // 19.5 KB
    __shared__ float sadj[N_][N_];
    int g = blockIdx.x + g0, tid = threadIdx.x;
    for (int i = tid; i < N_ * N_; i += 256)
        ((float*)sadj)[i] = g_adjn[(size_t)g * N_ * N_ + i];
    int bb = g / T_, tt = g - bb * T_;
    long tb = (long)bb * N_ * T_ * D_ + (long)tt * D_;
    // vectorized: 8 floats per task -> 8 halfs (uint4 STS)
    for (int task = tid; task < N_ * 64; task += 256) {
        int n = task >> 6, d0 = (task & 63) << 3;
        const float* fp = src + tb + (long)n * T_ * D_ + d0;
        float4 f0 = *(const float4*)(fp);
        float4 f1 = *(const float4*)(fp + 4);
        union { uint4 q; __half h[8]; } H;
        H.h[0] = __float2half_rn(f0.x); H.h[1] = __float2half_rn(f0.y);
        H.h[2] = __float2half_rn(f0.z); H.h[3] = __float2half_rn(f0.w);
        H.h[4] = __float2half_rn(f1.x); H.h[5] = __float2half_rn(f1.y);
        H.h[6] = __float2half_rn(f1.z); H.h[7] = __float2half_rn(f1.w);
        *reinterpret_cast<uint4*>(&xs[n][d0]) = H.q;
    }
    __syncthreads();
    do_mix_split(xs, sadj, g, tid);
}

// ---------------- fused: layer-0 LN/GELU + layer-1 mix ----------------------
__global__ __launch_bounds__(256)
void lnmix_kernel(const __half* __restrict__ y,
                  const float* __restrict__ features,
                  const float* __restrict__ gamma, const float* __restrict__ beta,
                  const float* __restrict__ bias, int g0)
{
    __shared__ __half xs[N_][D_];        // 19.5 KB
    __shared__ float sadj[N_][N_];
    int g = blockIdx.x + g0, tid = threadIdx.x;
    int wid = tid >> 5, lane = tid & 31;
    for (int i = tid; i < N_ * N_; i += 256)
        ((float*)sadj)[i] = g_adjn[(size_t)g * N_ * N_ + i];

    int bb = g / T_, tt = g - bb * T_;
    const long tb = (long)bb * N_ * T_ * D_ + (long)tt * D_;

    for (int r = wid; r < N_; r += 8) {
        const long row = (long)g * N_ + r;
        const __half* yp = y + row * D_;
        const float* rp = features + tb + (long)r * T_ * D_;
        float v[16];
        float sum = 0.0f, sq = 0.0f;
        #pragma unroll
        for (int i = 0; i < 4; i++) {
            int c = lane * 4 + i * 128;
            float a[4];
            ldh4(yp + c, a);
            float4 r4 = *(const float4*)(rp + c);
            float4 b4 = *(const float4*)(bias + c);
            float t0 = a[0] + b4.x + r4.x, t1 = a[1] + b4.y + r4.y;
            float t2 = a[2] + b4.z + r4.z, t3 = a[3] + b4.w + r4.w;
            v[i*4+0] = t0; v[i*4+1] = t1; v[i*4+2] = t2; v[i*4+3] = t3;
            sum += t0 + t1 + t2 + t3;
            sq = fmaf(t0, t0, sq); sq = fmaf(t1, t1, sq);
            sq = fmaf(t2, t2, sq); sq = fmaf(t3, t3, sq);
        }
        #pragma unroll
        for (int o = 16; o; o >>= 1) {
            sum += __shfl_xor_sync(0xffffffffu, sum, o);
            sq  += __shfl_xor_sync(0xffffffffu, sq, o);
        }
        float mu = sum * (1.0f / D_);
        float var = sq * (1.0f / D_) - mu * mu;
        float rstd = rsqrtf(var + LN_EPS);
        __half* sp = g_state + row * D_;
        #pragma unroll
        for (int i = 0; i < 4; i++) {
            int c = lane * 4 + i * 128;
            float4 g4 = *(const float4*)(gamma + c);
            float4 be4 = *(const float4*)(beta + c);
            float o0 = fmaf((v[i*4+0] - mu) * rstd, g4.x, be4.x);
            float o1 = fmaf((v[i*4+1] - mu) * rstd, g4.y, be4.y);
            float o2 = fmaf((v[i*4+2] - mu) * rstd, g4.z, be4.z);
            float o3 = fmaf((v[i*4+3] - mu) * rstd, g4.w, be4.w);
            o0 = 0.5f * o0 * (1.0f + erff(o0 * 0.70710678118654752f));
            o1 = 0.5f * o1 * (1.0f + erff(o1 * 0.70710678118654752f));
            o2 = 0.5f * o2 * (1.0f + erff(o2 * 0.70710678118654752f));
            o3 = 0.5f * o3 * (1.0f + erff(o3 * 0.70710678118654752f));
            __half2 h0 = __floats2half2_rn(o0, o1);
            __half2 h1 = __floats2half2_rn(o2, o3);
            uint2 q;
            q.x = *reinterpret_cast<uint32_t*>(&h0);
            q.y = *reinterpret_cast<uint32_t*>(&h1);
            *reinterpret_cast<uint2*>(&xs[r][c]) = q;   // fp16 xs == state values
            *reinterpret_cast<uint2*>(sp + c) = q;
        }
    }
    __syncthreads();
    do_mix_split(xs, sadj, g, tid);
}

// ---------------- GEMM: 128x128, single fp16 term, 2 CTA/SM -----------------
__global__ __launch_bounds__(256, 2)
void gemm_kernel(const unsigned char* __restrict__ gA,
                 const unsigned char* __restrict__ gB,
                 __half* __restrict__ y, int mt0)
{
    extern __shared__ unsigned char smraw[];
    __shared__ __align__(8) unsigned long long s_mbar[NSTAGES];

    const int tid = threadIdx.x, wid = tid >> 5, lane = tid & 31;
    const int wm = wid >> 1, wn = wid & 1;
    const int mtile = (blockIdx.x >> 2) + mt0, nt = blockIdx.x & 3;

    const uint32_t base = (smem_u32(smraw) + 1023) & ~1023u;
    uint32_t mb[NSTAGES];
    #pragma unroll
    for (int i = 0; i < NSTAGES; i++) mb[i] = smem_u32(&s_mbar[0]) + 8 * i;
    if (tid == 0)
        for (int i = 0; i < NSTAGES; i++) MBAR_INIT(mb[i], 1);
    __syncthreads();

    const unsigned char* pA = gA + (size_t)mtile * KCHUNKS * ATILE_BYTES;
    const unsigned char* pB = gB + (size_t)nt * BTILE_BYTES;

    const uint32_t a_rowoff = (wm * 32 + (lane & 15)) * 128;
    const uint32_t a_klane = (uint32_t)(lane >> 4) << 4;
    const uint32_t b_rowoff = (wn * 64 + ((lane >> 4) << 3) + (lane & 7)) * 128;
    const uint32_t b_klane = (uint32_t)((lane >> 3) & 1) << 4;
    const uint32_t cswz = (uint32_t)(lane & 7) << 4;

    float acc[2][8][4];
    #pragma unroll
    for (int ms = 0; ms < 2; ms++)
        #pragma unroll
        for (int ns = 0; ns < 8; ns++)
            #pragma unroll
            for (int q = 0; q < 4; q++) acc[ms][ns][q] = 0.0f;

    if (tid == 0) {
        #pragma unroll
        for (int s = 0; s < 2; s++) {
            const uint32_t st = base + s * STAGE_BYTES;
            MBAR_EXPECT(mb[s], (uint32_t)STAGE_BYTES);
            bulk_g2s(st,         pA + (size_t)s * ATILE_BYTES, ATILE_BYTES, mb[s]);
            bulk_g2s(st + 16384, pB + (size_t)s * NTILES * BTILE_BYTES, BTILE_BYTES, mb[s]);
        }
    }

    for (int kc = 0; kc < KCHUNKS; kc++) {
        const int slot = kc % NSTAGES;
        MBAR_WAIT(mb[slot], (kc / NSTAGES) & 1);
        __syncthreads();
        if (tid == 0 && kc + 2 < KCHUNKS) {
            const int kn = kc + 2, sl = kn % NSTAGES;
            const uint32_t st = base + sl * STAGE_BYTES;
            MBAR_EXPECT(mb[sl], (uint32_t)STAGE_BYTES);
            bulk_g2s(st,         pA + (size_t)kn * ATILE_BYTES, ATILE_BYTES, mb[sl]);
            bulk_g2s(st + 16384, pB + (size_t)kn * NTILES * BTILE_BYTES, BTILE_BYTES, mb[sl]);
        }
        const uint32_t st = base + slot * STAGE_BYTES;
        const uint32_t sA = st, sB = st + 16384;

        #pragma unroll
        for (int ks = 0; ks < 4; ks++) {
            const uint32_t akb = ((uint32_t)(ks * 32) + a_klane) ^ cswz;
            const uint32_t bkb = ((uint32_t)(ks * 32) + b_klane) ^ cswz;
            uint32_t av[2][4];
            LDX4(av[0], sA + a_rowoff + akb);
            LDX4(av[1], sA + a_rowoff + 2048 + akb);
            uint32_t bv[4][4];
            #pragma unroll
            for (int nb = 0; nb < 4; nb++)
                LDX4(bv[nb], sB + b_rowoff + nb * 2048 + bkb);
            #pragma unroll
            for (int ms = 0; ms < 2; ms++) {
                #pragma unroll
                for (int ns = 0; ns < 8; ns++) {
                    const uint32_t* BB = &bv[ns >> 1][(ns & 1) * 2];
                    MMA(acc[ms][ns], av[ms], BB[0], BB[1]);
                }
            }
        }
    }

    const int mrow = mtile * 128 + wm * 32;
    const int ncol = nt * 128 + wn * 64;
    #pragma unroll
    for (int ms = 0; ms < 2; ms++) {
        const int r0 = mrow + ms * 16 + (lane >> 2);
        const int r1 = r0 + 8;
        #pragma unroll
        for (int ns = 0; ns < 8; ns++) {
            const int c = ncol + ns * 8 + (lane & 3) * 2;
            if (r0 < NROWS) {
                __half2 h = __floats2half2_rn(acc[ms][ns][0], acc[ms][ns][1]);
                *(__half2*)(y + (size_t)r0 * D_ + c) = h;
            }
            if (r1 < NROWS) {
                __half2 h = __floats2half2_rn(acc[ms][ns][2], acc[ms][ns][3]);
                *(__half2*)(y + (size_t)r1 * D_ + c) = h;
            }
        }
    }
}

// ---------------- final: bias + residual + LN + exact GELU -> out ------------
__global__ __launch_bounds__(256)
void ln_kernel(const __half* __restrict__ y,
               const __half* __restrict__ res,
               float* __restrict__ dst,
               const float* __restrict__ gamma, const float* __restrict__ beta,
               const float* __restrict__ bias, int blk0)
{
    int row = (blockIdx.x + blk0) * 8 + (threadIdx.x >> 5);
    int lane = threadIdx.x & 31;
    if (row >= NROWS) return;
    int g = row / N_, n = row - g * N_;
    int bb = g / T_, tt = g - bb * T_;
    long toff = ((long)(bb * N_ + n) * T_ + tt) * D_;

    const __half* rp = res + (long)row * D_;
    float* dp = dst + toff;
    const __half* yp = y + (long)row * D_;

    float v[16];
    float sum = 0.0f, sq = 0.0f;
    #pragma unroll
    for (int i = 0; i < 4; i++) {
        int c = lane * 4 + i * 128;
        float a[4], r4[4];
        ldh4(yp + c, a);
        ldh4(rp + c, r4);
        float4 b4 = *(const float4*)(bias + c);
        float t0 = a[0] + b4.x + r4[0], t1 = a[1] + b4.y + r4[1];
        float t2 = a[2] + b4.z + r4[2], t3 = a[3] + b4.w + r4[3];
        v[i*4+0] = t0; v[i*4+1] = t1; v[i*4+2] = t2; v[i*4+3] = t3;
        sum += t0 + t1 + t2 + t3;
        sq = fmaf(t0, t0, sq); sq = fmaf(t1, t1, sq);
        sq = fmaf(t2, t2, sq); sq = fmaf(t3, t3, sq);
    }
    #pragma unroll
    for (int o = 16; o; o >>= 1) {
        sum += __shfl_xor_sync(0xffffffffu, sum, o);
        sq  += __shfl_xor_sync(0xffffffffu, sq, o);
    }
    float mu = sum * (1.0f / D_);
    float var = sq * (1.0f / D_) - mu * mu;
    float rstd = rsqrtf(var + LN_EPS);
    #pragma unroll
    for (int i = 0; i < 4; i++) {
        int c = lane * 4 + i * 128;
        float4 g4 = *(const float4*)(gamma + c);
        float4 be4 = *(const float4*)(beta + c);
        float o0 = fmaf((v[i*4+0] - mu) * rstd, g4.x, be4.x);
        float o1 = fmaf((v[i*4+1] - mu) * rstd, g4.y, be4.y);
        float o2 = fmaf((v[i*4+2] - mu) * rstd, g4.z, be4.z);
        float o3 = fmaf((v[i*4+3] - mu) * rstd, g4.w, be4.w);
        o0 = 0.5f * o0 * (1.0f + erff(o0 * 0.70710678118654752f));
        o1 = 0.5f * o1 * (1.0f + erff(o1 * 0.70710678118654752f));
        o2 = 0.5f * o2 * (1.0f + erff(o2 * 0.70710678118654752f));
        o3 = 0.5f * o3 * (1.0f + erff(o3 * 0.70710678118654752f));
        *(float4*)(dp + c) = make_float4(o0, o1, o2, o3);
    }
}

// ---------------- streams/events ---------------------------------------------
struct GcmStreams {
    cudaStream_t s1, s2;
    cudaEvent_t e_root, e_w, e1, e2;
    GcmStreams() {
        cudaStreamCreateWithFlags(&s1, cudaStreamNonBlocking);
        cudaStreamCreateWithFlags(&s2, cudaStreamNonBlocking);
        cudaEventCreateWithFlags(&e_root, cudaEventDisableTiming);
        cudaEventCreateWithFlags(&e_w, cudaEventDisableTiming);
        cudaEventCreateWithFlags(&e1, cudaEventDisableTiming);
        cudaEventCreateWithFlags(&e2, cudaEventDisableTiming);
    }
};
static GcmStreams g_str;

// ---------------- launch -----------------------------------------------------
extern "C" void kernel_launch(void* const* d_in, const int* in_sizes, int n_in,
                              void* d_out, int out_size)
{
    const float* features  = (const float*)d_in[0];
    const float* adjacency = (const float*)d_in[1];
    const float* edge_w    = (const float*)d_in[2];
    const float* edge_b    = (const float*)d_in[3];
    const float* W         = (const float*)d_in[4];
    const float* bias      = (const float*)d_in[5];
    const float* gamma     = (const float*)d_in[6];
    const float* beta      = (const float*)d_in[7];
    float* out = (float*)d_out;

    unsigned char *av, *bv;
    __half *yv, *state;
    cudaGetSymbolAddress((void**)&av, g_a);
    cudaGetSymbolAddress((void**)&bv, g_b);
    cudaGetSymbolAddress((void**)&yv, g_y);
    cudaGetSymbolAddress((void**)&state, g_state);

    cudaFuncSetAttribute(gemm_kernel, cudaFuncAttributeMaxDynamicSharedMemorySize,
                         GEMM_SMEM_DYN);

    const size_t bl = (size_t)KCHUNKS * NTILES * BTILE_BYTES;
    cudaStream_t s1 = g_str.s1, s2 = g_str.s2;

    cudaEventRecord(g_str.e_root, 0);
    cudaStreamWaitEvent(s1, g_str.e_root, 0);
    cudaStreamWaitEvent(s2, g_str.e_root, 0);

    // ---- chain X on s1 -------------------------------------------------------
    wconv_kernel<<<256, 256, 0, s1>>>(W);
    cudaEventRecord(g_str.e_w, s1);
    adj_kernel<<<G1, 128, 0, s1>>>(adjacency, edge_w, edge_b, 0);
    mix_kernel<<<G1, 256, 0, s1>>>(features, 0);
    gemm_kernel<<<MT1 * NTILES, 256, GEMM_SMEM_DYN, s1>>>(av, bv, yv, 0);
    lnmix_kernel<<<G1, 256, 0, s1>>>(yv, features, gamma, beta, bias, 0);
    gemm_kernel<<<MT1 * NTILES, 256, GEMM_SMEM_DYN, s1>>>(av, bv + bl, yv, 0);
    ln_kernel<<<LNB1, 256, 0, s1>>>(yv, state, out, gamma + D_, beta + D_,
                                    bias + D_, 0);
    cudaEventRecord(g_str.e1, s1);

    // ---- chain Y on s2 -------------------------------------------------------
    adj_kernel<<<G2, 128, 0, s2>>>(adjacency, edge_w, edge_b, G1);
    mix_kernel<<<G2, 256, 0, s2>>>(features, G1);
    cudaStreamWaitEvent(s2, g_str.e_w, 0);
    gemm_kernel<<<MT2 * NTILES, 256, GEMM_SMEM_DYN, s2>>>(av, bv, yv, MT1);
    lnmix_kernel<<<G2, 256, 0, s2>>>(yv, features, gamma, beta, bias, G1);
    gemm_kernel<<<MT2 * NTILES, 256, GEMM_SMEM_DYN, s2>>>(av, bv + bl, yv, MT1);
    ln_kernel<<<LNB2, 256, 0, s2>>>(yv, state, out, gamma + D_, beta + D_,
                                    bias + D_, LNB1);
    cudaEventRecord(g_str.e2, s2);

    cudaStreamWaitEvent(0, g_str.e1, 0);
    cudaStreamWaitEvent(0, g_str.e2, 0);
}

// round 15
// speedup vs baseline: 1.5631x; 1.0018x over previous
#include <cuda_runtime.h>
#include <cuda_fp16.h>
#include <math.h>
#include <stdint.h>

#define B_ 8
#define N_ 19
#define T_ 1000
#define D_ 512
#define ALPHA 0.05f
#define LN_EPS 1e-5f
#define ROW_EPS 1e-6f

#define NGRAPH (B_ * T_)       // 8000
#define NROWS (NGRAPH * N_)    // 152000
#define MTILES 1188
#define NTILES 4
#define KCHUNKS 8
#define ATILE_BYTES 16384
#define BTILE_BYTES 16384
#define STAGE_BYTES 32768
#define NSTAGES 3
#define GEMM_SMEM_DYN (NSTAGES * STAGE_BYTES + 1024)

// chain split
#define G1 4096
#define G2 (NGRAPH - G1)
#define MT1 608
#define MT2 (MTILES - MT1)
#define LNB1 (G1 * N_ / 8)
#define LNB2 ((NROWS - G1 * N_ + 7) / 8)

// ---------------- scratch ----------------------------------------------------
__device__ __align__(16) unsigned char g_a[(size_t)MTILES * KCHUNKS * ATILE_BYTES];
__device__ __align__(16) unsigned char g_b[2 * KCHUNKS * NTILES * BTILE_BYTES];
__device__ float g_adjn[(size_t)NGRAPH * N_ * N_];
__device__ __align__(16) __half g_state[(size_t)NROWS * D_];
__device__ __align__(16) __half g_y[(size_t)MTILES * 128 * D_];

// ---------------- helpers ---------------------------------------------------
__device__ __forceinline__ uint32_t swz(uint32_t o) { return o ^ ((o >> 3) & 0x70); }

__device__ __forceinline__ uint32_t smem_u32(const void* p) {
    uint32_t a;
    asm("{ .reg .u64 t; cvta.to.shared.u64 t, %1; cvt.u32.u64 %0, t; }" : "=r"(a) : "l"(p));
    return a;
}
__device__ __forceinline__ void bulk_g2s(uint32_t dst, const void* src,
                                         uint32_t bytes, uint32_t mbar) {
    asm volatile(
        "cp.async.bulk.shared::cta.global.mbarrier::complete_tx::bytes [%0], [%1], %2, [%3];"
        :: "r"(dst), "l"(src), "r"(bytes), "r"(mbar) : "memory");
}
#define MBAR_INIT(a, c) asm volatile("mbarrier.init.shared.b64 [%0], %1;" :: "r"(a), "r"(c) : "memory")
#define MBAR_EXPECT(a, b) asm volatile("mbarrier.arrive.expect_tx.shared.b64 _, [%0], %1;" :: "r"(a), "r"(b) : "memory")
#define MBAR_WAIT(addr, ph) do {                                                      \
    asm volatile(                                                                     \
        "{\n\t.reg .pred P;\n\t"                                                      \
        "WL_%=:\n\t"                                                                  \
        "mbarrier.try_wait.parity.acquire.cta.shared::cta.b64 P, [%0], %1, 0x989680;\n\t" \
        "@P bra.uni WD_%=;\n\t"                                                       \
        "bra.uni WL_%=;\n\t"                                                          \
        "WD_%=:\n\t}"                                                                 \
        :: "r"(addr), "r"(ph) : "memory");                                            \
} while (0)

#define LDX4(r, a)                                                                    \
    asm volatile("ldmatrix.sync.aligned.m8n8.x4.shared.b16 {%0,%1,%2,%3}, [%4];"      \
        : "=r"((r)[0]), "=r"((r)[1]), "=r"((r)[2]), "=r"((r)[3]) : "r"(a))

#define MMA(c, a, b0v, b1v)                                                           \
    asm volatile("mma.sync.aligned.m16n8k16.row.col.f32.f16.f16.f32 "                 \
        "{%0,%1,%2,%3},{%4,%5,%6,%7},{%8,%9},{%0,%1,%2,%3};"                          \
        : "+f"((c)[0]), "+f"((c)[1]), "+f"((c)[2]), "+f"((c)[3])                      \
        : "r"((a)[0]), "r"((a)[1]), "r"((a)[2]), "r"((a)[3]), "r"(b0v), "r"(b1v))

__device__ __forceinline__ void ldh4_cs(const __half* p, float* f) {
    uint2 q = __ldcs(reinterpret_cast<const uint2*>(p));
    __half2 h0 = *reinterpret_cast<__half2*>(&q.x);
    __half2 h1 = *reinterpret_cast<__half2*>(&q.y);
    float2 a = __half22float2(h0), b = __half22float2(h1);
    f[0] = a.x; f[1] = a.y; f[2] = b.x; f[3] = b.y;
}
__device__ __forceinline__ void h8tof(uint4 q, float* f) {
    __half2 h0 = *reinterpret_cast<__half2*>(&q.x);
    __half2 h1 = *reinterpret_cast<__half2*>(&q.y);
    __half2 h2 = *reinterpret_cast<__half2*>(&q.z);
    __half2 h3 = *reinterpret_cast<__half2*>(&q.w);
    float2 a = __half22float2(h0), b = __half22float2(h1);
    float2 c = __half22float2(h2), d = __half22float2(h3);
    f[0] = a.x; f[1] = a.y; f[2] = b.x; f[3] = b.y;
    f[4] = c.x; f[5] = c.y; f[6] = d.x; f[7] = d.y;
}

// ---------------- W -> fp16 W^T tiles ----------------------------------------
__global__ __launch_bounds__(256)
void wconv_kernel(const float* __restrict__ W)
{
    int p = blockIdx.x * 256 + threadIdx.x;
    if (p >= 2 * 512 * 64) return;
    int l = p >> 15;
    int rem = p & 32767;
    int n = rem >> 6;
    int k8 = rem & 63;
    int k0 = k8 * 8;
    const float* src = W + (size_t)l * D_ * D_ + n;
    union { uint4 q; __half h[8]; } H;
    #pragma unroll
    for (int i = 0; i < 8; i++)
        H.h[i] = __float2half_rn(src[(size_t)(k0 + i) * D_]);
    int kchunk = k0 >> 6, nq = n >> 7, nl = n & 127, kl = k0 & 63;
    size_t blk = (size_t)l * (KCHUNKS * NTILES) + kchunk * NTILES + nq;
    uint32_t off = swz((uint32_t)(nl * 128 + kl * 2));
    *(uint4*)(g_b + blk * BTILE_BYTES + off) = H.q;
}

// ---------------- shared mixing routine (xs fp16, conflict-free LDS.128) -----
__device__ __forceinline__ void do_mix_split(const __half (*xs)[D_],
                                             const float (*sadj)[N_],
                                             int g, int tid)
{
    for (int task = tid; task < N_ * 64; task += 256) {
        int n = task >> 6, k8 = task & 63, d0 = k8 << 3;
        float m[8];
        {
            float self[8];
            h8tof(*reinterpret_cast<const uint4*>(&xs[n][d0]), self);
            #pragma unroll
            for (int i = 0; i < 8; i++) m[i] = (1.0f - ALPHA) * self[i];
        }
        #pragma unroll
        for (int j = 0; j < N_; j++) {
            float a = ALPHA * sadj[n][j];
            float xj[8];
            h8tof(*reinterpret_cast<const uint4*>(&xs[j][d0]), xj);
            #pragma unroll
            for (int i = 0; i < 8; i++) m[i] = fmaf(a, xj[i], m[i]);
        }
        union { uint4 q; __half h[8]; } H;
        #pragma unroll
        for (int i = 0; i < 8; i++) H.h[i] = __float2half_rn(m[i]);
        int r = g * N_ + n;
        int mt = r >> 7, rl = r & 127;
        size_t blk = (size_t)mt * KCHUNKS + (k8 >> 3);
        uint32_t off = swz((uint32_t)(rl * 128 + (k8 & 7) * 16));
        *(uint4*)(g_a + blk * ATILE_BYTES + off) = H.q;
    }
}

// ---------------- layer-0 mix (adj fused in; writes g_adjn for lnmix) --------
__global__ __launch_bounds__(256)
void mix_kernel(const float* __restrict__ src,
                const float* __restrict__ adjacency,
                const float* __restrict__ edge_w, const float* __restrict__ edge_b,
                int g0)
{
    __shared__ __half xs[N_][D_];
    __shared__ float sadj[N_][N_];
    int g = blockIdx.x + g0, tid = threadIdx.x;

    // adjacency: softplus + row-normalize (fused, replaces adj_kernel)
    {
        float ew = edge_w[0], eb = edge_b[0];
        const float* a = adjacency + (size_t)g * N_ * N_;
        for (int i = tid; i < N_ * N_; i += 256) {
            float v = fmaf(__ldcs(a + i), ew, eb);
            ((float*)sadj)[i] = fmaxf(v, 0.0f) + log1pf(expf(-fabsf(v)));
        }
    }
    __syncthreads();
    if (tid < N_) {
        float sum = 0.0f;
        #pragma unroll
        for (int j = 0; j < N_; j++) sum += sadj[tid][j];
        float inv = 1.0f / (sum + ROW_EPS);
        #pragma unroll
        for (int j = 0; j < N_; j++) sadj[tid][j] *= inv;
    }

    int bb = g / T_, tt = g - bb * T_;
    long tb = (long)bb * N_ * T_ * D_ + (long)tt * D_;
    // load features fp32 -> fp16 xs (overlaps the tid<19 normalize via separate sync below)
    __syncthreads();
    for (int task = tid; task < N_ * 64; task += 256) {
        int n = task >> 6, d0 = (task & 63) << 3;
        const float* fp = src + tb + (long)n * T_ * D_ + d0;
        float4 f0 = __ldcs((const float4*)(fp));
        float4 f1 = __ldcs((const float4*)(fp + 4));
        union { uint4 q; __half h[8]; } H;
        H.h[0] = __float2half_rn(f0.x); H.h[1] = __float2half_rn(f0.y);
        H.h[2] = __float2half_rn(f0.z); H.h[3] = __float2half_rn(f0.w);
        H.h[4] = __float2half_rn(f1.x); H.h[5] = __float2half_rn(f1.y);
        H.h[6] = __float2half_rn(f1.z); H.h[7] = __float2half_rn(f1.w);
        *reinterpret_cast<uint4*>(&xs[n][d0]) = H.q;
    }
    // save normalized adj for lnmix
    for (int i = tid; i < N_ * N_; i += 256)
        g_adjn[(size_t)g * N_ * N_ + i] = ((float*)sadj)[i];
    __syncthreads();
    do_mix_split(xs, sadj, g, tid);
}

// ---------------- fused: layer-0 LN/GELU + layer-1 mix ----------------------
__global__ __launch_bounds__(256)
void lnmix_kernel(const __half* __restrict__ y,
                  const float* __restrict__ features,
                  const float* __restrict__ gamma, const float* __restrict__ beta,
                  const float* __restrict__ bias, int g0)
{
    __shared__ __half xs[N_][D_];
    __shared__ float sadj[N_][N_];
    int g = blockIdx.x + g0, tid = threadIdx.x;
    int wid = tid >> 5, lane = tid & 31;
    for (int i = tid; i < N_ * N_; i += 256)
        ((float*)sadj)[i] = g_adjn[(size_t)g * N_ * N_ + i];

    int bb = g / T_, tt = g - bb * T_;
    const long tb = (long)bb * N_ * T_ * D_ + (long)tt * D_;

    for (int r = wid; r < N_; r += 8) {
        const long row = (long)g * N_ + r;
        const __half* yp = y + row * D_;
        const float* rp = features + tb + (long)r * T_ * D_;
        float v[16];
        float sum = 0.0f, sq = 0.0f;
        #pragma unroll
        for (int i = 0; i < 4; i++) {
            int c = lane * 4 + i * 128;
            float a[4];
            ldh4_cs(yp + c, a);
            float4 r4 = __ldcs((const float4*)(rp + c));
            float4 b4 = *(const float4*)(bias + c);
            float t0 = a[0] + b4.x + r4.x, t1 = a[1] + b4.y + r4.y;
            float t2 = a[2] + b4.z + r4.z, t3 = a[3] + b4.w + r4.w;
            v[i*4+0] = t0; v[i*4+1] = t1; v[i*4+2] = t2; v[i*4+3] = t3;
            sum += t0 + t1 + t2 + t3;
            sq = fmaf(t0, t0, sq); sq = fmaf(t1, t1, sq);
            sq = fmaf(t2, t2, sq); sq = fmaf(t3, t3, sq);
        }
        #pragma unroll
        for (int o = 16; o; o >>= 1) {
            sum += __shfl_xor_sync(0xffffffffu, sum, o);
            sq  += __shfl_xor_sync(0xffffffffu, sq, o);
        }
        float mu = sum * (1.0f / D_);
        float var = sq * (1.0f / D_) - mu * mu;
        float rstd = rsqrtf(var + LN_EPS);
        __half* sp = g_state + row * D_;
        #pragma unroll
        for (int i = 0; i < 4; i++) {
            int c = lane * 4 + i * 128;
            float4 g4 = *(const float4*)(gamma + c);
            float4 be4 = *(const float4*)(beta + c);
            float o0 = fmaf((v[i*4+0] - mu) * rstd, g4.x, be4.x);
            float o1 = fmaf((v[i*4+1] - mu) * rstd, g4.y, be4.y);
            float o2 = fmaf((v[i*4+2] - mu) * rstd, g4.z, be4.z);
            float o3 = fmaf((v[i*4+3] - mu) * rstd, g4.w, be4.w);
            o0 = 0.5f * o0 * (1.0f + erff(o0 * 0.70710678118654752f));
            o1 = 0.5f * o1 * (1.0f + erff(o1 * 0.70710678118654752f));
            o2 = 0.5f * o2 * (1.0f + erff(o2 * 0.70710678118654752f));
            o3 = 0.5f * o3 * (1.0f + erff(o3 * 0.70710678118654752f));
            __half2 h0 = __floats2half2_rn(o0, o1);
            __half2 h1 = __floats2half2_rn(o2, o3);
            uint2 q;
            q.x = *reinterpret_cast<uint32_t*>(&h0);
            q.y = *reinterpret_cast<uint32_t*>(&h1);
            *reinterpret_cast<uint2*>(&xs[r][c]) = q;
            __stcs(reinterpret_cast<uint2*>(sp + c), q);
        }
    }
    __syncthreads();
    do_mix_split(xs, sadj, g, tid);
}

// ---------------- GEMM: 128x128, single fp16 term, 2 CTA/SM -----------------
__global__ __launch_bounds__(256, 2)
void gemm_kernel(const unsigned char* __restrict__ gA,
                 const unsigned char* __restrict__ gB,
                 __half* __restrict__ y, int mt0)
{
    extern __shared__ unsigned char smraw[];
    __shared__ __align__(8) unsigned long long s_mbar[NSTAGES];

    const int tid = threadIdx.x, wid = tid >> 5, lane = tid & 31;
    const int wm = wid >> 1, wn = wid & 1;
    const int mtile = (blockIdx.x >> 2) + mt0, nt = blockIdx.x & 3;

    const uint32_t base = (smem_u32(smraw) + 1023) & ~1023u;
    uint32_t mb[NSTAGES];
    #pragma unroll
    for (int i = 0; i < NSTAGES; i++) mb[i] = smem_u32(&s_mbar[0]) + 8 * i;
    if (tid == 0)
        for (int i = 0; i < NSTAGES; i++) MBAR_INIT(mb[i], 1);
    __syncthreads();

    const unsigned char* pA = gA + (size_t)mtile * KCHUNKS * ATILE_BYTES;
    const unsigned char* pB = gB + (size_t)nt * BTILE_BYTES;

    const uint32_t a_rowoff = (wm * 32 + (lane & 15)) * 128;
    const uint32_t a_klane = (uint32_t)(lane >> 4) << 4;
    const uint32_t b_rowoff = (wn * 64 + ((lane >> 4) << 3) + (lane & 7)) * 128;
    const uint32_t b_klane = (uint32_t)((lane >> 3) & 1) << 4;
    const uint32_t cswz = (uint32_t)(lane & 7) << 4;

    float acc[2][8][4];
    #pragma unroll
    for (int ms = 0; ms < 2; ms++)
        #pragma unroll
        for (int ns = 0; ns < 8; ns++)
            #pragma unroll
            for (int q = 0; q < 4; q++) acc[ms][ns][q] = 0.0f;

    if (tid == 0) {
        #pragma unroll
        for (int s = 0; s < 2; s++) {
            const uint32_t st = base + s * STAGE_BYTES;
            MBAR_EXPECT(mb[s], (uint32_t)STAGE_BYTES);
            bulk_g2s(st,         pA + (size_t)s * ATILE_BYTES, ATILE_BYTES, mb[s]);
            bulk_g2s(st + 16384, pB + (size_t)s * NTILES * BTILE_BYTES, BTILE_BYTES, mb[s]);
        }
    }

    for (int kc = 0; kc < KCHUNKS; kc++) {
        const int slot = kc % NSTAGES;
        MBAR_WAIT(mb[slot], (kc / NSTAGES) & 1);
        __syncthreads();
        if (tid == 0 && kc + 2 < KCHUNKS) {
            const int kn = kc + 2, sl = kn % NSTAGES;
            const uint32_t st = base + sl * STAGE_BYTES;
            MBAR_EXPECT(mb[sl], (uint32_t)STAGE_BYTES);
            bulk_g2s(st,         pA + (size_t)kn * ATILE_BYTES, ATILE_BYTES, mb[sl]);
            bulk_g2s(st + 16384, pB + (size_t)kn * NTILES * BTILE_BYTES, BTILE_BYTES, mb[sl]);
        }
        const uint32_t st = base + slot * STAGE_BYTES;
        const uint32_t sA = st, sB = st + 16384;

        #pragma unroll
        for (int ks = 0; ks < 4; ks++) {
            const uint32_t akb = ((uint32_t)(ks * 32) + a_klane) ^ cswz;
            const uint32_t bkb = ((uint32_t)(ks * 32) + b_klane) ^ cswz;
            uint32_t av[2][4];
            LDX4(av[0], sA + a_rowoff + akb);
            LDX4(av[1], sA + a_rowoff + 2048 + akb);
            uint32_t bv[4][4];
            #pragma unroll
            for (int nb = 0; nb < 4; nb++)
                LDX4(bv[nb], sB + b_rowoff + nb * 2048 + bkb);
            #pragma unroll
            for (int ms = 0; ms < 2; ms++) {
                #pragma unroll
                for (int ns = 0; ns < 8; ns++) {
                    const uint32_t* BB = &bv[ns >> 1][(ns & 1) * 2];
                    MMA(acc[ms][ns], av[ms], BB[0], BB[1]);
                }
            }
        }
    }

    const int mrow = mtile * 128 + wm * 32;
    const int ncol = nt * 128 + wn * 64;
    #pragma unroll
    for (int ms = 0; ms < 2; ms++) {
        const int r0 = mrow + ms * 16 + (lane >> 2);
        const int r1 = r0 + 8;
        #pragma unroll
        for (int ns = 0; ns < 8; ns++) {
            const int c = ncol + ns * 8 + (lane & 3) * 2;
            if (r0 < NROWS) {
                __half2 h = __floats2half2_rn(acc[ms][ns][0], acc[ms][ns][1]);
                *(__half2*)(y + (size_t)r0 * D_ + c) = h;
            }
            if (r1 < NROWS) {
                __half2 h = __floats2half2_rn(acc[ms][ns][2], acc[ms][ns][3]);
                *(__half2*)(y + (size_t)r1 * D_ + c) = h;
            }
        }
    }
}

// ---------------- final: bias + residual + LN + exact GELU -> out ------------
__global__ __launch_bounds__(256)
void ln_kernel(const __half* __restrict__ y,
               const __half* __restrict__ res,
               float* __restrict__ dst,
               const float* __restrict__ gamma, const float* __restrict__ beta,
               const float* __restrict__ bias, int blk0)
{
    int row = (blockIdx.x + blk0) * 8 + (threadIdx.x >> 5);
    int lane = threadIdx.x & 31;
    if (row >= NROWS) return;
    int g = row / N_, n = row - g * N_;
    int bb = g / T_, tt = g - bb * T_;
    long toff = ((long)(bb * N_ + n) * T_ + tt) * D_;

    const __half* rp = res + (long)row * D_;
    float* dp = dst + toff;
    const __half* yp = y + (long)row * D_;

    float v[16];
    float sum = 0.0f, sq = 0.0f;
    #pragma unroll
    for (int i = 0; i < 4; i++) {
        int c = lane * 4 + i * 128;
        float a[4], r4[4];
        ldh4_cs(yp + c, a);
        ldh4_cs(rp + c, r4);
        float4 b4 = *(const float4*)(bias + c);
        float t0 = a[0] + b4.x + r4[0], t1 = a[1] + b4.y + r4[1];
        float t2 = a[2] + b4.z + r4[2], t3 = a[3] + b4.w + r4[3];
        v[i*4+0] = t0; v[i*4+1] = t1; v[i*4+2] = t2; v[i*4+3] = t3;
        sum += t0 + t1 + t2 + t3;
        sq = fmaf(t0, t0, sq); sq = fmaf(t1, t1, sq);
        sq = fmaf(t2, t2, sq); sq = fmaf(t3, t3, sq);
    }
    #pragma unroll
    for (int o = 16; o; o >>= 1) {
        sum += __shfl_xor_sync(0xffffffffu, sum, o);
        sq  += __shfl_xor_sync(0xffffffffu, sq, o);
    }
    float mu = sum * (1.0f / D_);
    float var = sq * (1.0f / D_) - mu * mu;
    float rstd = rsqrtf(var + LN_EPS);
    #pragma unroll
    for (int i = 0; i < 4; i++) {
        int c = lane * 4 + i * 128;
        float4 g4 = *(const float4*)(gamma + c);
        float4 be4 = *(const float4*)(beta + c);
        float o0 = fmaf((v[i*4+0] - mu) * rstd, g4.x, be4.x);
        float o1 = fmaf((v[i*4+1] - mu) * rstd, g4.y, be4.y);
        float o2 = fmaf((v[i*4+2] - mu) * rstd, g4.z, be4.z);
        float o3 = fmaf((v[i*4+3] - mu) * rstd, g4.w, be4.w);
        o0 = 0.5f * o0 * (1.0f + erff(o0 * 0.70710678118654752f));
        o1 = 0.5f * o1 * (1.0f + erff(o1 * 0.70710678118654752f));
        o2 = 0.5f * o2 * (1.0f + erff(o2 * 0.70710678118654752f));
        o3 = 0.5f * o3 * (1.0f + erff(o3 * 0.70710678118654752f));
        __stcs((float4*)(dp + c), make_float4(o0, o1, o2, o3));
    }
}

// ---------------- streams/events ---------------------------------------------
struct GcmStreams {
    cudaStream_t s1, s2;
    cudaEvent_t e_root, e_w, e1, e2;
    GcmStreams() {
        cudaStreamCreateWithFlags(&s1, cudaStreamNonBlocking);
        cudaStreamCreateWithFlags(&s2, cudaStreamNonBlocking);
        cudaEventCreateWithFlags(&e_root, cudaEventDisableTiming);
        cudaEventCreateWithFlags(&e_w, cudaEventDisableTiming);
        cudaEventCreateWithFlags(&e1, cudaEventDisableTiming);
        cudaEventCreateWithFlags(&e2, cudaEventDisableTiming);
    }
};
static GcmStreams g_str;

// ---------------- launch -----------------------------------------------------
extern "C" void kernel_launch(void* const* d_in, const int* in_sizes, int n_in,
                              void* d_out, int out_size)
{
    const float* features  = (const float*)d_in[0];
    const float* adjacency = (const float*)d_in[1];
    const float* edge_w    = (const float*)d_in[2];
    const float* edge_b    = (const float*)d_in[3];
    const float* W         = (const float*)d_in[4];
    const float* bias      = (const float*)d_in[5];
    const float* gamma     = (const float*)d_in[6];
    const float* beta      = (const float*)d_in[7];
    float* out = (float*)d_out;

    unsigned char *av, *bv;
    __half *yv, *state;
    cudaGetSymbolAddress((void**)&av, g_a);
    cudaGetSymbolAddress((void**)&bv, g_b);
    cudaGetSymbolAddress((void**)&yv, g_y);
    cudaGetSymbolAddress((void**)&state, g_state);

    cudaFuncSetAttribute(gemm_kernel, cudaFuncAttributeMaxDynamicSharedMemorySize,
                         GEMM_SMEM_DYN);

    const size_t bl = (size_t)KCHUNKS * NTILES * BTILE_BYTES;
    cudaStream_t s1 = g_str.s1, s2 = g_str.s2;

    cudaEventRecord(g_str.e_root, 0);
    cudaStreamWaitEvent(s1, g_str.e_root, 0);
    cudaStreamWaitEvent(s2, g_str.e_root, 0);

    // ---- chain X on s1 -------------------------------------------------------
    wconv_kernel<<<256, 256, 0, s1>>>(W);
    cudaEventRecord(g_str.e_w, s1);
    mix_kernel<<<G1, 256, 0, s1>>>(features, adjacency, edge_w, edge_b, 0);
    gemm_kernel<<<MT1 * NTILES, 256, GEMM_SMEM_DYN, s1>>>(av, bv, yv, 0);
    lnmix_kernel<<<G1, 256, 0, s1>>>(yv, features, gamma, beta, bias, 0);
    gemm_kernel<<<MT1 * NTILES, 256, GEMM_SMEM_DYN, s1>>>(av, bv + bl, yv, 0);
    ln_kernel<<<LNB1, 256, 0, s1>>>(yv, state, out, gamma + D_, beta + D_,
                                    bias + D_, 0);
    cudaEventRecord(g_str.e1, s1);

    // ---- chain Y on s2 -------------------------------------------------------
    mix_kernel<<<G2, 256, 0, s2>>>(features, adjacency, edge_w, edge_b, G1);
    cudaStreamWaitEvent(s2, g_str.e_w, 0);
    gemm_kernel<<<MT2 * NTILES, 256, GEMM_SMEM_DYN, s2>>>(av, bv, yv, MT1);
    lnmix_kernel<<<G2, 256, 0, s2>>>(yv, features, gamma, beta, bias, G1);
    gemm_kernel<<<MT2 * NTILES, 256, GEMM_SMEM_DYN, s2>>>(av, bv + bl, yv, MT1);
    ln_kernel<<<LNB2, 256, 0, s2>>>(yv, state, out, gamma + D_, beta + D_,
                                    bias + D_, LNB1);
    cudaEventRecord(g_str.e2, s2);

    cudaStreamWaitEvent(0, g_str.e1, 0);
    cudaStreamWaitEvent(0, g_str.e2, 0);
}

// round 16
// speedup vs baseline: 1.8087x; 1.1571x over previous
#include <cuda_runtime.h>
#include <cuda_fp16.h>
#include <math.h>
#include <stdint.h>

#define B_ 8
#define N_ 19
#define T_ 1000
#define D_ 512
#define ALPHA 0.05f
#define LN_EPS 1e-5f
#define ROW_EPS 1e-6f

#define NGRAPH (B_ * T_)       // 8000
#define NROWS (NGRAPH * N_)    // 152000
#define MTILES 1188
#define NTILES 4
#define KCHUNKS 8
#define ATILE_BYTES 16384
#define BTILE_BYTES 16384
#define STAGE_BYTES 32768
#define NSTAGES 3
#define GEMM_SMEM_DYN (NSTAGES * STAGE_BYTES + 1024)

// chain split
#define G1 4096
#define G2 (NGRAPH - G1)
#define MT1 608
#define MT2 (MTILES - MT1)
#define LNB1 (G1 * N_ / 8)
#define LNB2 ((NROWS - G1 * N_ + 7) / 8)

// ---------------- scratch ----------------------------------------------------
__device__ __align__(16) unsigned char g_a[(size_t)MTILES * KCHUNKS * ATILE_BYTES];
__device__ __align__(16) unsigned char g_b[2 * KCHUNKS * NTILES * BTILE_BYTES];
__device__ float g_adjn[(size_t)NGRAPH * N_ * N_];
__device__ __align__(16) __half g_state[(size_t)NROWS * D_];
__device__ __align__(16) __half g_y[(size_t)MTILES * 128 * D_];

// ---------------- helpers ---------------------------------------------------
__device__ __forceinline__ uint32_t swz(uint32_t o) { return o ^ ((o >> 3) & 0x70); }

__device__ __forceinline__ uint32_t smem_u32(const void* p) {
    uint32_t a;
    asm("{ .reg .u64 t; cvta.to.shared.u64 t, %1; cvt.u32.u64 %0, t; }" : "=r"(a) : "l"(p));
    return a;
}
__device__ __forceinline__ void bulk_g2s(uint32_t dst, const void* src,
                                         uint32_t bytes, uint32_t mbar) {
    asm volatile(
        "cp.async.bulk.shared::cta.global.mbarrier::complete_tx::bytes [%0], [%1], %2, [%3];"
        :: "r"(dst), "l"(src), "r"(bytes), "r"(mbar) : "memory");
}
#define MBAR_INIT(a, c) asm volatile("mbarrier.init.shared.b64 [%0], %1;" :: "r"(a), "r"(c) : "memory")
#define MBAR_EXPECT(a, b) asm volatile("mbarrier.arrive.expect_tx.shared.b64 _, [%0], %1;" :: "r"(a), "r"(b) : "memory")
#define MBAR_WAIT(addr, ph) do {                                                      \
    asm volatile(                                                                     \
        "{\n\t.reg .pred P;\n\t"                                                      \
        "WL_%=:\n\t"                                                                  \
        "mbarrier.try_wait.parity.acquire.cta.shared::cta.b64 P, [%0], %1, 0x989680;\n\t" \
        "@P bra.uni WD_%=;\n\t"                                                       \
        "bra.uni WL_%=;\n\t"                                                          \
        "WD_%=:\n\t}"                                                                 \
        :: "r"(addr), "r"(ph) : "memory");                                            \
} while (0)

#define LDX4(r, a)                                                                    \
    asm volatile("ldmatrix.sync.aligned.m8n8.x4.shared.b16 {%0,%1,%2,%3}, [%4];"      \
        : "=r"((r)[0]), "=r"((r)[1]), "=r"((r)[2]), "=r"((r)[3]) : "r"(a))

#define MMA(c, a, b0v, b1v)                                                           \
    asm volatile("mma.sync.aligned.m16n8k16.row.col.f32.f16.f16.f32 "                 \
        "{%0,%1,%2,%3},{%4,%5,%6,%7},{%8,%9},{%0,%1,%2,%3};"                          \
        : "+f"((c)[0]), "+f"((c)[1]), "+f"((c)[2]), "+f"((c)[3])                      \
        : "r"((a)[0]), "r"((a)[1]), "r"((a)[2]), "r"((a)[3]), "r"(b0v), "r"(b1v))

__device__ __forceinline__ void ldh4_cs(const __half* p, float* f) {
    uint2 q = __ldcs(reinterpret_cast<const uint2*>(p));
    __half2 h0 = *reinterpret_cast<__half2*>(&q.x);
    __half2 h1 = *reinterpret_cast<__half2*>(&q.y);
    float2 a = __half22float2(h0), b = __half22float2(h1);
    f[0] = a.x; f[1] = a.y; f[2] = b.x; f[3] = b.y;
}
// unpack 4 halfs (uint2) -> 4 floats
__device__ __forceinline__ void h4tof(uint2 q, float* f) {
    __half2 h0 = *reinterpret_cast<__half2*>(&q.x);
    __half2 h1 = *reinterpret_cast<__half2*>(&q.y);
    float2 a = __half22float2(h0), b = __half22float2(h1);
    f[0] = a.x; f[1] = a.y; f[2] = b.x; f[3] = b.y;
}

// ---------------- W -> fp16 W^T tiles ----------------------------------------
__global__ __launch_bounds__(256)
void wconv_kernel(const float* __restrict__ W)
{
    int p = blockIdx.x * 256 + threadIdx.x;
    if (p >= 2 * 512 * 64) return;
    int l = p >> 15;
    int rem = p & 32767;
    int n = rem >> 6;
    int k8 = rem & 63;
    int k0 = k8 * 8;
    const float* src = W + (size_t)l * D_ * D_ + n;
    union { uint4 q; __half h[8]; } H;
    #pragma unroll
    for (int i = 0; i < 8; i++)
        H.h[i] = __float2half_rn(src[(size_t)(k0 + i) * D_]);
    int kchunk = k0 >> 6, nq = n >> 7, nl = n & 127, kl = k0 & 63;
    size_t blk = (size_t)l * (KCHUNKS * NTILES) + kchunk * NTILES + nq;
    uint32_t off = swz((uint32_t)(nl * 128 + kl * 2));
    *(uint4*)(g_b + blk * BTILE_BYTES + off) = H.q;
}

// ---------------- shared mixing routine (4-wide tasks, low reg pressure) -----
// task = (row n, 4-half group). xs loads are uint2 (8B), conflict-light.
// swizzle note: sub-16B offset (bit 3) passes through swz() unchanged.
__device__ __forceinline__ void do_mix_split(const __half (*xs)[D_],
                                             const float (*sadj)[N_],
                                             int g, int tid)
{
    for (int task = tid; task < N_ * 128; task += 256) {
        int n = task >> 7, k4 = task & 127, d0 = k4 << 2;
        float m[4];
        {
            float self[4];
            h4tof(*reinterpret_cast<const uint2*>(&xs[n][d0]), self);
            #pragma unroll
            for (int i = 0; i < 4; i++) m[i] = (1.0f - ALPHA) * self[i];
        }
        #pragma unroll
        for (int j = 0; j < N_; j++) {
            float a = ALPHA * sadj[n][j];
            float xj[4];
            h4tof(*reinterpret_cast<const uint2*>(&xs[j][d0]), xj);
            #pragma unroll
            for (int i = 0; i < 4; i++) m[i] = fmaf(a, xj[i], m[i]);
        }
        union { uint2 q; __half h[4]; } H;
        #pragma unroll
        for (int i = 0; i < 4; i++) H.h[i] = __float2half_rn(m[i]);
        int r = g * N_ + n;
        int mt = r >> 7, rl = r & 127;
        int k8 = k4 >> 1;                 // 8-half group index
        size_t blk = (size_t)mt * KCHUNKS + (k8 >> 3);
        uint32_t off = swz((uint32_t)(rl * 128 + (k8 & 7) * 16)) + (uint32_t)((k4 & 1) * 8);
        *(uint2*)(g_a + blk * ATILE_BYTES + off) = H.q;
    }
}

// ---------------- layer-0 mix (adj fused; writes g_adjn for lnmix) -----------
__global__ __launch_bounds__(256, 2)
void mix_kernel(const float* __restrict__ src,
                const float* __restrict__ adjacency,
                const float* __restrict__ edge_w, const float* __restrict__ edge_b,
                int g0)
{
    __shared__ __half xs[N_][D_];
    __shared__ float sadj[N_][N_];
    int g = blockIdx.x + g0, tid = threadIdx.x;

    {
        float ew = edge_w[0], eb = edge_b[0];
        const float* a = adjacency + (size_t)g * N_ * N_;
        for (int i = tid; i < N_ * N_; i += 256) {
            float v = fmaf(__ldcs(a + i), ew, eb);
            ((float*)sadj)[i] = fmaxf(v, 0.0f) + log1pf(expf(-fabsf(v)));
        }
    }
    __syncthreads();
    if (tid < N_) {
        float sum = 0.0f;
        #pragma unroll
        for (int j = 0; j < N_; j++) sum += sadj[tid][j];
        float inv = 1.0f / (sum + ROW_EPS);
        #pragma unroll
        for (int j = 0; j < N_; j++) sadj[tid][j] *= inv;
    }

    int bb = g / T_, tt = g - bb * T_;
    long tb = (long)bb * N_ * T_ * D_ + (long)tt * D_;
    __syncthreads();
    for (int task = tid; task < N_ * 128; task += 256) {
        int n = task >> 7, d0 = (task & 127) << 2;
        const float* fp = src + tb + (long)n * T_ * D_ + d0;
        float4 f0 = __ldcs((const float4*)(fp));
        union { uint2 q; __half h[4]; } H;
        H.h[0] = __float2half_rn(f0.x); H.h[1] = __float2half_rn(f0.y);
        H.h[2] = __float2half_rn(f0.z); H.h[3] = __float2half_rn(f0.w);
        *reinterpret_cast<uint2*>(&xs[n][d0]) = H.q;
    }
    for (int i = tid; i < N_ * N_; i += 256)
        g_adjn[(size_t)g * N_ * N_ + i] = ((float*)sadj)[i];
    __syncthreads();
    do_mix_split(xs, sadj, g, tid);
}

// ---------------- fused: layer-0 LN/GELU + layer-1 mix ----------------------
__global__ __launch_bounds__(256, 2)
void lnmix_kernel(const __half* __restrict__ y,
                  const float* __restrict__ features,
                  const float* __restrict__ gamma, const float* __restrict__ beta,
                  const float* __restrict__ bias, int g0)
{
    __shared__ __half xs[N_][D_];
    __shared__ float sadj[N_][N_];
    int g = blockIdx.x + g0, tid = threadIdx.x;
    int wid = tid >> 5, lane = tid & 31;
    for (int i = tid; i < N_ * N_; i += 256)
        ((float*)sadj)[i] = g_adjn[(size_t)g * N_ * N_ + i];

    int bb = g / T_, tt = g - bb * T_;
    const long tb = (long)bb * N_ * T_ * D_ + (long)tt * D_;

    for (int r = wid; r < N_; r += 8) {
        const long row = (long)g * N_ + r;
        const __half* yp = y + row * D_;
        const float* rp = features + tb + (long)r * T_ * D_;
        float v[16];
        float sum = 0.0f, sq = 0.0f;
        #pragma unroll
        for (int i = 0; i < 4; i++) {
            int c = lane * 4 + i * 128;
            float a[4];
            ldh4_cs(yp + c, a);
            float4 r4 = __ldcs((const float4*)(rp + c));
            float4 b4 = *(const float4*)(bias + c);
            float t0 = a[0] + b4.x + r4.x, t1 = a[1] + b4.y + r4.y;
            float t2 = a[2] + b4.z + r4.z, t3 = a[3] + b4.w + r4.w;
            v[i*4+0] = t0; v[i*4+1] = t1; v[i*4+2] = t2; v[i*4+3] = t3;
            sum += t0 + t1 + t2 + t3;
            sq = fmaf(t0, t0, sq); sq = fmaf(t1, t1, sq);
            sq = fmaf(t2, t2, sq); sq = fmaf(t3, t3, sq);
        }
        #pragma unroll
        for (int o = 16; o; o >>= 1) {
            sum += __shfl_xor_sync(0xffffffffu, sum, o);
            sq  += __shfl_xor_sync(0xffffffffu, sq, o);
        }
        float mu = sum * (1.0f / D_);
        float var = sq * (1.0f / D_) - mu * mu;
        float rstd = rsqrtf(var + LN_EPS);
        __half* sp = g_state + row * D_;
        #pragma unroll
        for (int i = 0; i < 4; i++) {
            int c = lane * 4 + i * 128;
            float4 g4 = *(const float4*)(gamma + c);
            float4 be4 = *(const float4*)(beta + c);
            float o0 = fmaf((v[i*4+0] - mu) * rstd, g4.x, be4.x);
            float o1 = fmaf((v[i*4+1] - mu) * rstd, g4.y, be4.y);
            float o2 = fmaf((v[i*4+2] - mu) * rstd, g4.z, be4.z);
            float o3 = fmaf((v[i*4+3] - mu) * rstd, g4.w, be4.w);
            o0 = 0.5f * o0 * (1.0f + erff(o0 * 0.70710678118654752f));
            o1 = 0.5f * o1 * (1.0f + erff(o1 * 0.70710678118654752f));
            o2 = 0.5f * o2 * (1.0f + erff(o2 * 0.70710678118654752f));
            o3 = 0.5f * o3 * (1.0f + erff(o3 * 0.70710678118654752f));
            __half2 h0 = __floats2half2_rn(o0, o1);
            __half2 h1 = __floats2half2_rn(o2, o3);
            uint2 q;
            q.x = *reinterpret_cast<uint32_t*>(&h0);
            q.y = *reinterpret_cast<uint32_t*>(&h1);
            *reinterpret_cast<uint2*>(&xs[r][c]) = q;
            __stcs(reinterpret_cast<uint2*>(sp + c), q);
        }
    }
    __syncthreads();
    do_mix_split(xs, sadj, g, tid);
}

// ---------------- GEMM: 128x128, single fp16 term, 2 CTA/SM -----------------
__global__ __launch_bounds__(256, 2)
void gemm_kernel(const unsigned char* __restrict__ gA,
                 const unsigned char* __restrict__ gB,
                 __half* __restrict__ y, int mt0)
{
    extern __shared__ unsigned char smraw[];
    __shared__ __align__(8) unsigned long long s_mbar[NSTAGES];

    const int tid = threadIdx.x, wid = tid >> 5, lane = tid & 31;
    const int wm = wid >> 1, wn = wid & 1;
    const int mtile = (blockIdx.x >> 2) + mt0, nt = blockIdx.x & 3;

    const uint32_t base = (smem_u32(smraw) + 1023) & ~1023u;
    uint32_t mb[NSTAGES];
    #pragma unroll
    for (int i = 0; i < NSTAGES; i++) mb[i] = smem_u32(&s_mbar[0]) + 8 * i;
    if (tid == 0)
        for (int i = 0; i < NSTAGES; i++) MBAR_INIT(mb[i], 1);
    __syncthreads();

    const unsigned char* pA = gA + (size_t)mtile * KCHUNKS * ATILE_BYTES;
    const unsigned char* pB = gB + (size_t)nt * BTILE_BYTES;

    const uint32_t a_rowoff = (wm * 32 + (lane & 15)) * 128;
    const uint32_t a_klane = (uint32_t)(lane >> 4) << 4;
    const uint32_t b_rowoff = (wn * 64 + ((lane >> 4) << 3) + (lane & 7)) * 128;
    const uint32_t b_klane = (uint32_t)((lane >> 3) & 1) << 4;
    const uint32_t cswz = (uint32_t)(lane & 7) << 4;

    float acc[2][8][4];
    #pragma unroll
    for (int ms = 0; ms < 2; ms++)
        #pragma unroll
        for (int ns = 0; ns < 8; ns++)
            #pragma unroll
            for (int q = 0; q < 4; q++) acc[ms][ns][q] = 0.0f;

    if (tid == 0) {
        #pragma unroll
        for (int s = 0; s < 2; s++) {
            const uint32_t st = base + s * STAGE_BYTES;
            MBAR_EXPECT(mb[s], (uint32_t)STAGE_BYTES);
            bulk_g2s(st,         pA + (size_t)s * ATILE_BYTES, ATILE_BYTES, mb[s]);
            bulk_g2s(st + 16384, pB + (size_t)s * NTILES * BTILE_BYTES, BTILE_BYTES, mb[s]);
        }
    }

    for (int kc = 0; kc < KCHUNKS; kc++) {
        const int slot = kc % NSTAGES;
        MBAR_WAIT(mb[slot], (kc / NSTAGES) & 1);
        __syncthreads();
        if (tid == 0 && kc + 2 < KCHUNKS) {
            const int kn = kc + 2, sl = kn % NSTAGES;
            const uint32_t st = base + sl * STAGE_BYTES;
            MBAR_EXPECT(mb[sl], (uint32_t)STAGE_BYTES);
            bulk_g2s(st,         pA + (size_t)kn * ATILE_BYTES, ATILE_BYTES, mb[sl]);
            bulk_g2s(st + 16384, pB + (size_t)kn * NTILES * BTILE_BYTES, BTILE_BYTES, mb[sl]);
        }
        const uint32_t st = base + slot * STAGE_BYTES;
        const uint32_t sA = st, sB = st + 16384;

        #pragma unroll
        for (int ks = 0; ks < 4; ks++) {
            const uint32_t akb = ((uint32_t)(ks * 32) + a_klane) ^ cswz;
            const uint32_t bkb = ((uint32_t)(ks * 32) + b_klane) ^ cswz;
            uint32_t av[2][4];
            LDX4(av[0], sA + a_rowoff + akb);
            LDX4(av[1], sA + a_rowoff + 2048 + akb);
            uint32_t bv[4][4];
            #pragma unroll
            for (int nb = 0; nb < 4; nb++)
                LDX4(bv[nb], sB + b_rowoff + nb * 2048 + bkb);
            #pragma unroll
            for (int ms = 0; ms < 2; ms++) {
                #pragma unroll
                for (int ns = 0; ns < 8; ns++) {
                    const uint32_t* BB = &bv[ns >> 1][(ns & 1) * 2];
                    MMA(acc[ms][ns], av[ms], BB[0], BB[1]);
                }
            }
        }
    }

    const int mrow = mtile * 128 + wm * 32;
    const int ncol = nt * 128 + wn * 64;
    #pragma unroll
    for (int ms = 0; ms < 2; ms++) {
        const int r0 = mrow + ms * 16 + (lane >> 2);
        const int r1 = r0 + 8;
        #pragma unroll
        for (int ns = 0; ns < 8; ns++) {
            const int c = ncol + ns * 8 + (lane & 3) * 2;
            if (r0 < NROWS) {
                __half2 h = __floats2half2_rn(acc[ms][ns][0], acc[ms][ns][1]);
                *(__half2*)(y + (size_t)r0 * D_ + c) = h;
            }
            if (r1 < NROWS) {
                __half2 h = __floats2half2_rn(acc[ms][ns][2], acc[ms][ns][3]);
                *(__half2*)(y + (size_t)r1 * D_ + c) = h;
            }
        }
    }
}

// ---------------- final: bias + residual + LN + exact GELU -> out ------------
__global__ __launch_bounds__(256)
void ln_kernel(const __half* __restrict__ y,
               const __half* __restrict__ res,
               float* __restrict__ dst,
               const float* __restrict__ gamma, const float* __restrict__ beta,
               const float* __restrict__ bias, int blk0)
{
    int row = (blockIdx.x + blk0) * 8 + (threadIdx.x >> 5);
    int lane = threadIdx.x & 31;
    if (row >= NROWS) return;
    int g = row / N_, n = row - g * N_;
    int bb = g / T_, tt = g - bb * T_;
    long toff = ((long)(bb * N_ + n) * T_ + tt) * D_;

    const __half* rp = res + (long)row * D_;
    float* dp = dst + toff;
    const __half* yp = y + (long)row * D_;

    float v[16];
    float sum = 0.0f, sq = 0.0f;
    #pragma unroll
    for (int i = 0; i < 4; i++) {
        int c = lane * 4 + i * 128;
        float a[4], r4[4];
        ldh4_cs(yp + c, a);
        ldh4_cs(rp + c, r4);
        float4 b4 = *(const float4*)(bias + c);
        float t0 = a[0] + b4.x + r4[0], t1 = a[1] + b4.y + r4[1];
        float t2 = a[2] + b4.z + r4[2], t3 = a[3] + b4.w + r4[3];
        v[i*4+0] = t0; v[i*4+1] = t1; v[i*4+2] = t2; v[i*4+3] = t3;
        sum += t0 + t1 + t2 + t3;
        sq = fmaf(t0, t0, sq); sq = fmaf(t1, t1, sq);
        sq = fmaf(t2, t2, sq); sq = fmaf(t3, t3, sq);
    }
    #pragma unroll
    for (int o = 16; o; o >>= 1) {
        sum += __shfl_xor_sync(0xffffffffu, sum, o);
        sq  += __shfl_xor_sync(0xffffffffu, sq, o);
    }
    float mu = sum * (1.0f / D_);
    float var = sq * (1.0f / D_) - mu * mu;
    float rstd = rsqrtf(var + LN_EPS);
    #pragma unroll
    for (int i = 0; i < 4; i++) {
        int c = lane * 4 + i * 128;
        float4 g4 = *(const float4*)(gamma + c);
        float4 be4 = *(const float4*)(beta + c);
        float o0 = fmaf((v[i*4+0] - mu) * rstd, g4.x, be4.x);
        float o1 = fmaf((v[i*4+1] - mu) * rstd, g4.y, be4.y);
        float o2 = fmaf((v[i*4+2] - mu) * rstd, g4.z, be4.z);
        float o3 = fmaf((v[i*4+3] - mu) * rstd, g4.w, be4.w);
        o0 = 0.5f * o0 * (1.0f + erff(o0 * 0.70710678118654752f));
        o1 = 0.5f * o1 * (1.0f + erff(o1 * 0.70710678118654752f));
        o2 = 0.5f * o2 * (1.0f + erff(o2 * 0.70710678118654752f));
        o3 = 0.5f * o3 * (1.0f + erff(o3 * 0.70710678118654752f));
        __stcs((float4*)(dp + c), make_float4(o0, o1, o2, o3));
    }
}

// ---------------- streams/events ---------------------------------------------
struct GcmStreams {
    cudaStream_t s1, s2;
    cudaEvent_t e_root, e_w, e1, e2;
    GcmStreams() {
        cudaStreamCreateWithFlags(&s1, cudaStreamNonBlocking);
        cudaStreamCreateWithFlags(&s2, cudaStreamNonBlocking);
        cudaEventCreateWithFlags(&e_root, cudaEventDisableTiming);
        cudaEventCreateWithFlags(&e_w, cudaEventDisableTiming);
        cudaEventCreateWithFlags(&e1, cudaEventDisableTiming);
        cudaEventCreateWithFlags(&e2, cudaEventDisableTiming);
    }
};
static GcmStreams g_str;

// ---------------- launch -----------------------------------------------------
extern "C" void kernel_launch(void* const* d_in, const int* in_sizes, int n_in,
                              void* d_out, int out_size)
{
    const float* features  = (const float*)d_in[0];
    const float* adjacency = (const float*)d_in[1];
    const float* edge_w    = (const float*)d_in[2];
    const float* edge_b    = (const float*)d_in[3];
    const float* W         = (const float*)d_in[4];
    const float* bias      = (const float*)d_in[5];
    const float* gamma     = (const float*)d_in[6];
    const float* beta      = (const float*)d_in[7];
    float* out = (float*)d_out;

    unsigned char *av, *bv;
    __half *yv, *state;
    cudaGetSymbolAddress((void**)&av, g_a);
    cudaGetSymbolAddress((void**)&bv, g_b);
    cudaGetSymbolAddress((void**)&yv, g_y);
    cudaGetSymbolAddress((void**)&state, g_state);

    cudaFuncSetAttribute(gemm_kernel, cudaFuncAttributeMaxDynamicSharedMemorySize,
                         GEMM_SMEM_DYN);

    const size_t bl = (size_t)KCHUNKS * NTILES * BTILE_BYTES;
    cudaStream_t s1 = g_str.s1, s2 = g_str.s2;

    cudaEventRecord(g_str.e_root, 0);
    cudaStreamWaitEvent(s1, g_str.e_root, 0);
    cudaStreamWaitEvent(s2, g_str.e_root, 0);

    // ---- chain X on s1 -------------------------------------------------------
    wconv_kernel<<<256, 256, 0, s1>>>(W);
    cudaEventRecord(g_str.e_w, s1);
    mix_kernel<<<G1, 256, 0, s1>>>(features, adjacency, edge_w, edge_b, 0);
    gemm_kernel<<<MT1 * NTILES, 256, GEMM_SMEM_DYN, s1>>>(av, bv, yv, 0);
    lnmix_kernel<<<G1, 256, 0, s1>>>(yv, features, gamma, beta, bias, 0);
    gemm_kernel<<<MT1 * NTILES, 256, GEMM_SMEM_DYN, s1>>>(av, bv + bl, yv, 0);
    ln_kernel<<<LNB1, 256, 0, s1>>>(yv, state, out, gamma + D_, beta + D_,
                                    bias + D_, 0);
    cudaEventRecord(g_str.e1, s1);

    // ---- chain Y on s2 -------------------------------------------------------
    mix_kernel<<<G2, 256, 0, s2>>>(features, adjacency, edge_w, edge_b, G1);
    cudaStreamWaitEvent(s2, g_str.e_w, 0);
    gemm_kernel<<<MT2 * NTILES, 256, GEMM_SMEM_DYN, s2>>>(av, bv, yv, MT1);
    lnmix_kernel<<<G2, 256, 0, s2>>>(yv, features, gamma, beta, bias, G1);
    gemm_kernel<<<MT2 * NTILES, 256, GEMM_SMEM_DYN, s2>>>(av, bv + bl, yv, MT1);
    ln_kernel<<<LNB2, 256, 0, s2>>>(yv, state, out, gamma + D_, beta + D_,
                                    bias + D_, LNB1);
    cudaEventRecord(g_str.e2, s2);

    cudaStreamWaitEvent(0, g_str.e1, 0);
    cudaStreamWaitEvent(0, g_str.e2, 0);
}

// round 17
// speedup vs baseline: 1.8103x; 1.0009x over previous
#include <cuda_runtime.h>
#include <cuda_fp16.h>
#include <math.h>
#include <stdint.h>

#define B_ 8
#define N_ 19
#define T_ 1000
#define D_ 512
#define ALPHA 0.05f
#define LN_EPS 1e-5f
#define ROW_EPS 1e-6f

#define NGRAPH (B_ * T_)       // 8000
#define NROWS (NGRAPH * N_)    // 152000
#define MTILES 1188
#define NTILES 4
#define KCHUNKS 8
#define ATILE_BYTES 16384
#define BTILE_BYTES 16384
#define STAGE_BYTES 32768
#define NSTAGES 3
#define GEMM_SMEM_DYN (NSTAGES * STAGE_BYTES + 1024)

// chain split
#define G1 4096
#define G2 (NGRAPH - G1)
#define MT1 608
#define MT2 (MTILES - MT1)
#define LNB1 (G1 * N_ / 8)
#define LNB2 ((NROWS - G1 * N_ + 7) / 8)

// ---------------- scratch ----------------------------------------------------
__device__ __align__(16) unsigned char g_a[(size_t)MTILES * KCHUNKS * ATILE_BYTES];
__device__ __align__(16) unsigned char g_b[2 * KCHUNKS * NTILES * BTILE_BYTES];
__device__ float g_adjn[(size_t)NGRAPH * N_ * N_];
__device__ __align__(16) __half g_state[(size_t)NROWS * D_];
__device__ __align__(16) __half g_y[(size_t)MTILES * 128 * D_];

// ---------------- helpers ---------------------------------------------------
__device__ __forceinline__ uint32_t swz(uint32_t o) { return o ^ ((o >> 3) & 0x70); }

__device__ __forceinline__ uint32_t smem_u32(const void* p) {
    uint32_t a;
    asm("{ .reg .u64 t; cvta.to.shared.u64 t, %1; cvt.u32.u64 %0, t; }" : "=r"(a) : "l"(p));
    return a;
}
__device__ __forceinline__ void bulk_g2s(uint32_t dst, const void* src,
                                         uint32_t bytes, uint32_t mbar) {
    asm volatile(
        "cp.async.bulk.shared::cta.global.mbarrier::complete_tx::bytes [%0], [%1], %2, [%3];"
        :: "r"(dst), "l"(src), "r"(bytes), "r"(mbar) : "memory");
}
#define MBAR_INIT(a, c) asm volatile("mbarrier.init.shared.b64 [%0], %1;" :: "r"(a), "r"(c) : "memory")
#define MBAR_EXPECT(a, b) asm volatile("mbarrier.arrive.expect_tx.shared.b64 _, [%0], %1;" :: "r"(a), "r"(b) : "memory")
#define MBAR_WAIT(addr, ph) do {                                                      \
    asm volatile(                                                                     \
        "{\n\t.reg .pred P;\n\t"                                                      \
        "WL_%=:\n\t"                                                                  \
        "mbarrier.try_wait.parity.acquire.cta.shared::cta.b64 P, [%0], %1, 0x989680;\n\t" \
        "@P bra.uni WD_%=;\n\t"                                                       \
        "bra.uni WL_%=;\n\t"                                                          \
        "WD_%=:\n\t}"                                                                 \
        :: "r"(addr), "r"(ph) : "memory");                                            \
} while (0)

#define LDX4(r, a)                                                                    \
    asm volatile("ldmatrix.sync.aligned.m8n8.x4.shared.b16 {%0,%1,%2,%3}, [%4];"      \
        : "=r"((r)[0]), "=r"((r)[1]), "=r"((r)[2]), "=r"((r)[3]) : "r"(a))

#define MMA(c, a, b0v, b1v)                                                           \
    asm volatile("mma.sync.aligned.m16n8k16.row.col.f32.f16.f16.f32 "                 \
        "{%0,%1,%2,%3},{%4,%5,%6,%7},{%8,%9},{%0,%1,%2,%3};"                          \
        : "+f"((c)[0]), "+f"((c)[1]), "+f"((c)[2]), "+f"((c)[3])                      \
        : "r"((a)[0]), "r"((a)[1]), "r"((a)[2]), "r"((a)[3]), "r"(b0v), "r"(b1v))

__device__ __forceinline__ void ldh4_cs(const __half* p, float* f) {
    uint2 q = __ldcs(reinterpret_cast<const uint2*>(p));
    __half2 h0 = *reinterpret_cast<__half2*>(&q.x);
    __half2 h1 = *reinterpret_cast<__half2*>(&q.y);
    float2 a = __half22float2(h0), b = __half22float2(h1);
    f[0] = a.x; f[1] = a.y; f[2] = b.x; f[3] = b.y;
}
__device__ __forceinline__ void h4tof(uint2 q, float* f) {
    __half2 h0 = *reinterpret_cast<__half2*>(&q.x);
    __half2 h1 = *reinterpret_cast<__half2*>(&q.y);
    float2 a = __half22float2(h0), b = __half22float2(h1);
    f[0] = a.x; f[1] = a.y; f[2] = b.x; f[3] = b.y;
}

// ---------------- W -> fp16 W^T tiles ----------------------------------------
__global__ __launch_bounds__(256)
void wconv_kernel(const float* __restrict__ W)
{
    int p = blockIdx.x * 256 + threadIdx.x;
    if (p >= 2 * 512 * 64) return;
    int l = p >> 15;
    int rem = p & 32767;
    int n = rem >> 6;
    int k8 = rem & 63;
    int k0 = k8 * 8;
    const float* src = W + (size_t)l * D_ * D_ + n;
    union { uint4 q; __half h[8]; } H;
    #pragma unroll
    for (int i = 0; i < 8; i++)
        H.h[i] = __float2half_rn(src[(size_t)(k0 + i) * D_]);
    int kchunk = k0 >> 6, nq = n >> 7, nl = n & 127, kl = k0 & 63;
    size_t blk = (size_t)l * (KCHUNKS * NTILES) + kchunk * NTILES + nq;
    uint32_t off = swz((uint32_t)(nl * 128 + kl * 2));
    *(uint4*)(g_b + blk * BTILE_BYTES + off) = H.q;
}

// ---------------- mixing routine: row-pair tasks, 4-wide --------------------
// task = (row pair {2p, 2p+1}, 4-half column group). xj loads amortize over
// the two output rows. Arithmetic per output identical to single-row version.
__device__ __forceinline__ void do_mix_split(const __half (*xs)[D_],
                                             const float (*sadj)[N_],
                                             int g, int tid)
{
    for (int task = tid; task < 10 * 128; task += 256) {
        int p = task >> 7, k4 = task & 127, d0 = k4 << 2;
        int n0 = 2 * p, n1 = n0 + 1;
        const bool has1 = (n1 < N_);
        float m0[4], m1[4];
        {
            float s0[4];
            h4tof(*reinterpret_cast<const uint2*>(&xs[n0][d0]), s0);
            #pragma unroll
            for (int i = 0; i < 4; i++) m0[i] = (1.0f - ALPHA) * s0[i];
        }
        if (has1) {
            float s1[4];
            h4tof(*reinterpret_cast<const uint2*>(&xs[n1][d0]), s1);
            #pragma unroll
            for (int i = 0; i < 4; i++) m1[i] = (1.0f - ALPHA) * s1[i];
        }
        #pragma unroll
        for (int j = 0; j < N_; j++) {
            float xj[4];
            h4tof(*reinterpret_cast<const uint2*>(&xs[j][d0]), xj);
            float a0 = ALPHA * sadj[n0][j];
            #pragma unroll
            for (int i = 0; i < 4; i++) m0[i] = fmaf(a0, xj[i], m0[i]);
            if (has1) {
                float a1 = ALPHA * sadj[n1][j];
                #pragma unroll
                for (int i = 0; i < 4; i++) m1[i] = fmaf(a1, xj[i], m1[i]);
            }
        }
        int k8 = k4 >> 1;
        uint32_t suboff = (uint32_t)((k4 & 1) * 8);
        size_t blk_k = (size_t)(k8 >> 3) * ATILE_BYTES;
        uint32_t coloff = (uint32_t)((k8 & 7) * 16);
        {
            union { uint2 q; __half h[4]; } H;
            #pragma unroll
            for (int i = 0; i < 4; i++) H.h[i] = __float2half_rn(m0[i]);
            int r = g * N_ + n0;
            int mt = r >> 7, rl = r & 127;
            size_t blk = (size_t)mt * KCHUNKS * ATILE_BYTES + blk_k;
            uint32_t off = swz((uint32_t)(rl * 128) + coloff) + suboff;
            *(uint2*)(g_a + blk + off) = H.q;
        }
        if (has1) {
            union { uint2 q; __half h[4]; } H;
            #pragma unroll
            for (int i = 0; i < 4; i++) H.h[i] = __float2half_rn(m1[i]);
            int r = g * N_ + n1;
            int mt = r >> 7, rl = r & 127;
            size_t blk = (size_t)mt * KCHUNKS * ATILE_BYTES + blk_k;
            uint32_t off = swz((uint32_t)(rl * 128) + coloff) + suboff;
            *(uint2*)(g_a + blk + off) = H.q;
        }
    }
}

// ---------------- layer-0 mix (adj fused; writes g_adjn for lnmix) -----------
__global__ __launch_bounds__(256, 2)
void mix_kernel(const float* __restrict__ src,
                const float* __restrict__ adjacency,
                const float* __restrict__ edge_w, const float* __restrict__ edge_b,
                int g0)
{
    __shared__ __half xs[N_][D_];
    __shared__ float sadj[N_][N_];
    int g = blockIdx.x + g0, tid = threadIdx.x;

    {
        float ew = edge_w[0], eb = edge_b[0];
        const float* a = adjacency + (size_t)g * N_ * N_;
        for (int i = tid; i < N_ * N_; i += 256) {
            float v = fmaf(__ldcs(a + i), ew, eb);
            ((float*)sadj)[i] = fmaxf(v, 0.0f) + log1pf(expf(-fabsf(v)));
        }
    }
    __syncthreads();
    if (tid < N_) {
        float sum = 0.0f;
        #pragma unroll
        for (int j = 0; j < N_; j++) sum += sadj[tid][j];
        float inv = 1.0f / (sum + ROW_EPS);
        #pragma unroll
        for (int j = 0; j < N_; j++) sadj[tid][j] *= inv;
    }

    int bb = g / T_, tt = g - bb * T_;
    long tb = (long)bb * N_ * T_ * D_ + (long)tt * D_;
    __syncthreads();
    for (int task = tid; task < N_ * 128; task += 256) {
        int n = task >> 7, d0 = (task & 127) << 2;
        const float* fp = src + tb + (long)n * T_ * D_ + d0;
        float4 f0 = __ldcs((const float4*)(fp));
        union { uint2 q; __half h[4]; } H;
        H.h[0] = __float2half_rn(f0.x); H.h[1] = __float2half_rn(f0.y);
        H.h[2] = __float2half_rn(f0.z); H.h[3] = __float2half_rn(f0.w);
        *reinterpret_cast<uint2*>(&xs[n][d0]) = H.q;
    }
    for (int i = tid; i < N_ * N_; i += 256)
        g_adjn[(size_t)g * N_ * N_ + i] = ((float*)sadj)[i];
    __syncthreads();
    do_mix_split(xs, sadj, g, tid);
}

// ---------------- fused: layer-0 LN/GELU + layer-1 mix ----------------------
__global__ __launch_bounds__(256, 2)
void lnmix_kernel(const __half* __restrict__ y,
                  const float* __restrict__ features,
                  const float* __restrict__ gamma, const float* __restrict__ beta,
                  const float* __restrict__ bias, int g0)
{
    __shared__ __half xs[N_][D_];
    __shared__ float sadj[N_][N_];
    int g = blockIdx.x + g0, tid = threadIdx.x;
    int wid = tid >> 5, lane = tid & 31;
    for (int i = tid; i < N_ * N_; i += 256)
        ((float*)sadj)[i] = g_adjn[(size_t)g * N_ * N_ + i];

    int bb = g / T_, tt = g - bb * T_;
    const long tb = (long)bb * N_ * T_ * D_ + (long)tt * D_;

    for (int r = wid; r < N_; r += 8) {
        const long row = (long)g * N_ + r;
        const __half* yp = y + row * D_;
        const float* rp = features + tb + (long)r * T_ * D_;
        float v[16];
        float sum = 0.0f, sq = 0.0f;
        #pragma unroll
        for (int i = 0; i < 4; i++) {
            int c = lane * 4 + i * 128;
            float a[4];
            ldh4_cs(yp + c, a);
            float4 r4 = __ldcs((const float4*)(rp + c));
            float4 b4 = *(const float4*)(bias + c);
            float t0 = a[0] + b4.x + r4.x, t1 = a[1] + b4.y + r4.y;
            float t2 = a[2] + b4.z + r4.z, t3 = a[3] + b4.w + r4.w;
            v[i*4+0] = t0; v[i*4+1] = t1; v[i*4+2] = t2; v[i*4+3] = t3;
            sum += t0 + t1 + t2 + t3;
            sq = fmaf(t0, t0, sq); sq = fmaf(t1, t1, sq);
            sq = fmaf(t2, t2, sq); sq = fmaf(t3, t3, sq);
        }
        #pragma unroll
        for (int o = 16; o; o >>= 1) {
            sum += __shfl_xor_sync(0xffffffffu, sum, o);
            sq  += __shfl_xor_sync(0xffffffffu, sq, o);
        }
        float mu = sum * (1.0f / D_);
        float var = sq * (1.0f / D_) - mu * mu;
        float rstd = rsqrtf(var + LN_EPS);
        __half* sp = g_state + row * D_;
        #pragma unroll
        for (int i = 0; i < 4; i++) {
            int c = lane * 4 + i * 128;
            float4 g4 = *(const float4*)(gamma + c);
            float4 be4 = *(const float4*)(beta + c);
            float o0 = fmaf((v[i*4+0] - mu) * rstd, g4.x, be4.x);
            float o1 = fmaf((v[i*4+1] - mu) * rstd, g4.y, be4.y);
            float o2 = fmaf((v[i*4+2] - mu) * rstd, g4.z, be4.z);
            float o3 = fmaf((v[i*4+3] - mu) * rstd, g4.w, be4.w);
            o0 = 0.5f * o0 * (1.0f + erff(o0 * 0.70710678118654752f));
            o1 = 0.5f * o1 * (1.0f + erff(o1 * 0.70710678118654752f));
            o2 = 0.5f * o2 * (1.0f + erff(o2 * 0.70710678118654752f));
            o3 = 0.5f * o3 * (1.0f + erff(o3 * 0.70710678118654752f));
            __half2 h0 = __floats2half2_rn(o0, o1);
            __half2 h1 = __floats2half2_rn(o2, o3);
            uint2 q;
            q.x = *reinterpret_cast<uint32_t*>(&h0);
            q.y = *reinterpret_cast<uint32_t*>(&h1);
            *reinterpret_cast<uint2*>(&xs[r][c]) = q;
            __stcs(reinterpret_cast<uint2*>(sp + c), q);
        }
    }
    __syncthreads();
    do_mix_split(xs, sadj, g, tid);
}

// ---------------- GEMM: 128x128, single fp16 term, 2 CTA/SM -----------------
__global__ __launch_bounds__(256, 2)
void gemm_kernel(const unsigned char* __restrict__ gA,
                 const unsigned char* __restrict__ gB,
                 __half* __restrict__ y, int mt0)
{
    extern __shared__ unsigned char smraw[];
    __shared__ __align__(8) unsigned long long s_mbar[NSTAGES];

    const int tid = threadIdx.x, wid = tid >> 5, lane = tid & 31;
    const int wm = wid >> 1, wn = wid & 1;
    const int mtile = (blockIdx.x >> 2) + mt0, nt = blockIdx.x & 3;

    const uint32_t base = (smem_u32(smraw) + 1023) & ~1023u;
    uint32_t mb[NSTAGES];
    #pragma unroll
    for (int i = 0; i < NSTAGES; i++) mb[i] = smem_u32(&s_mbar[0]) + 8 * i;
    if (tid == 0)
        for (int i = 0; i < NSTAGES; i++) MBAR_INIT(mb[i], 1);
    __syncthreads();

    const unsigned char* pA = gA + (size_t)mtile * KCHUNKS * ATILE_BYTES;
    const unsigned char* pB = gB + (size_t)nt * BTILE_BYTES;

    const uint32_t a_rowoff = (wm * 32 + (lane & 15)) * 128;
    const uint32_t a_klane = (uint32_t)(lane >> 4) << 4;
    const uint32_t b_rowoff = (wn * 64 + ((lane >> 4) << 3) + (lane & 7)) * 128;
    const uint32_t b_klane = (uint32_t)((lane >> 3) & 1) << 4;
    const uint32_t cswz = (uint32_t)(lane & 7) << 4;

    float acc[2][8][4];
    #pragma unroll
    for (int ms = 0; ms < 2; ms++)
        #pragma unroll
        for (int ns = 0; ns < 8; ns++)
            #pragma unroll
            for (int q = 0; q < 4; q++) acc[ms][ns][q] = 0.0f;

    if (tid == 0) {
        #pragma unroll
        for (int s = 0; s < 2; s++) {
            const uint32_t st = base + s * STAGE_BYTES;
            MBAR_EXPECT(mb[s], (uint32_t)STAGE_BYTES);
            bulk_g2s(st,         pA + (size_t)s * ATILE_BYTES, ATILE_BYTES, mb[s]);
            bulk_g2s(st + 16384, pB + (size_t)s * NTILES * BTILE_BYTES, BTILE_BYTES, mb[s]);
        }
    }

    for (int kc = 0; kc < KCHUNKS; kc++) {
        const int slot = kc % NSTAGES;
        MBAR_WAIT(mb[slot], (kc / NSTAGES) & 1);
        __syncthreads();
        if (tid == 0 && kc + 2 < KCHUNKS) {
            const int kn = kc + 2, sl = kn % NSTAGES;
            const uint32_t st = base + sl * STAGE_BYTES;
            MBAR_EXPECT(mb[sl], (uint32_t)STAGE_BYTES);
            bulk_g2s(st,         pA + (size_t)kn * ATILE_BYTES, ATILE_BYTES, mb[sl]);
            bulk_g2s(st + 16384, pB + (size_t)kn * NTILES * BTILE_BYTES, BTILE_BYTES, mb[sl]);
        }
        const uint32_t st = base + slot * STAGE_BYTES;
        const uint32_t sA = st, sB = st + 16384;

        #pragma unroll
        for (int ks = 0; ks < 4; ks++) {
            const uint32_t akb = ((uint32_t)(ks * 32) + a_klane) ^ cswz;
            const uint32_t bkb = ((uint32_t)(ks * 32) + b_klane) ^ cswz;
            uint32_t av[2][4];
            LDX4(av[0], sA + a_rowoff + akb);
            LDX4(av[1], sA + a_rowoff + 2048 + akb);
            uint32_t bv[4][4];
            #pragma unroll
            for (int nb = 0; nb < 4; nb++)
                LDX4(bv[nb], sB + b_rowoff + nb * 2048 + bkb);
            #pragma unroll
            for (int ms = 0; ms < 2; ms++) {
                #pragma unroll
                for (int ns = 0; ns < 8; ns++) {
                    const uint32_t* BB = &bv[ns >> 1][(ns & 1) * 2];
                    MMA(acc[ms][ns], av[ms], BB[0], BB[1]);
                }
            }
        }
    }

    const int mrow = mtile * 128 + wm * 32;
    const int ncol = nt * 128 + wn * 64;
    #pragma unroll
    for (int ms = 0; ms < 2; ms++) {
        const int r0 = mrow + ms * 16 + (lane >> 2);
        const int r1 = r0 + 8;
        #pragma unroll
        for (int ns = 0; ns < 8; ns++) {
            const int c = ncol + ns * 8 + (lane & 3) * 2;
            if (r0 < NROWS) {
                __half2 h = __floats2half2_rn(acc[ms][ns][0], acc[ms][ns][1]);
                *(__half2*)(y + (size_t)r0 * D_ + c) = h;
            }
            if (r1 < NROWS) {
                __half2 h = __floats2half2_rn(acc[ms][ns][2], acc[ms][ns][3]);
                *(__half2*)(y + (size_t)r1 * D_ + c) = h;
            }
        }
    }
}

// ---------------- final: bias + residual + LN + exact GELU -> out ------------
__global__ __launch_bounds__(256)
void ln_kernel(const __half* __restrict__ y,
               const __half* __restrict__ res,
               float* __restrict__ dst,
               const float* __restrict__ gamma, const float* __restrict__ beta,
               const float* __restrict__ bias, int blk0)
{
    int row = (blockIdx.x + blk0) * 8 + (threadIdx.x >> 5);
    int lane = threadIdx.x & 31;
    if (row >= NROWS) return;
    int g = row / N_, n = row - g * N_;
    int bb = g / T_, tt = g - bb * T_;
    long toff = ((long)(bb * N_ + n) * T_ + tt) * D_;

    const __half* rp = res + (long)row * D_;
    float* dp = dst + toff;
    const __half* yp = y + (long)row * D_;

    float v[16];
    float sum = 0.0f, sq = 0.0f;
    #pragma unroll
    for (int i = 0; i < 4; i++) {
        int c = lane * 4 + i * 128;
        float a[4], r4[4];
        ldh4_cs(yp + c, a);
        ldh4_cs(rp + c, r4);
        float4 b4 = *(const float4*)(bias + c);
        float t0 = a[0] + b4.x + r4[0], t1 = a[1] + b4.y + r4[1];
        float t2 = a[2] + b4.z + r4[2], t3 = a[3] + b4.w + r4[3];
        v[i*4+0] = t0; v[i*4+1] = t1; v[i*4+2] = t2; v[i*4+3] = t3;
        sum += t0 + t1 + t2 + t3;
        sq = fmaf(t0, t0, sq); sq = fmaf(t1, t1, sq);
        sq = fmaf(t2, t2, sq); sq = fmaf(t3, t3, sq);
    }
    #pragma unroll
    for (int o = 16; o; o >>= 1) {
        sum += __shfl_xor_sync(0xffffffffu, sum, o);
        sq  += __shfl_xor_sync(0xffffffffu, sq, o);
    }
    float mu = sum * (1.0f / D_);
    float var = sq * (1.0f / D_) - mu * mu;
    float rstd = rsqrtf(var + LN_EPS);
    #pragma unroll
    for (int i = 0; i < 4; i++) {
        int c = lane * 4 + i * 128;
        float4 g4 = *(const float4*)(gamma + c);
        float4 be4 = *(const float4*)(beta + c);
        float o0 = fmaf((v[i*4+0] - mu) * rstd, g4.x, be4.x);
        float o1 = fmaf((v[i*4+1] - mu) * rstd, g4.y, be4.y);
        float o2 = fmaf((v[i*4+2] - mu) * rstd, g4.z, be4.z);
        float o3 = fmaf((v[i*4+3] - mu) * rstd, g4.w, be4.w);
        o0 = 0.5f * o0 * (1.0f + erff(o0 * 0.70710678118654752f));
        o1 = 0.5f * o1 * (1.0f + erff(o1 * 0.70710678118654752f));
        o2 = 0.5f * o2 * (1.0f + erff(o2 * 0.70710678118654752f));
        o3 = 0.5f * o3 * (1.0f + erff(o3 * 0.70710678118654752f));
        __stcs((float4*)(dp + c), make_float4(o0, o1, o2, o3));
    }
}

// ---------------- streams/events ---------------------------------------------
struct GcmStreams {
    cudaStream_t s1, s2;
    cudaEvent_t e_root, e_w, e1, e2;
    GcmStreams() {
        cudaStreamCreateWithFlags(&s1, cudaStreamNonBlocking);
        cudaStreamCreateWithFlags(&s2, cudaStreamNonBlocking);
        cudaEventCreateWithFlags(&e_root, cudaEventDisableTiming);
        cudaEventCreateWithFlags(&e_w, cudaEventDisableTiming);
        cudaEventCreateWithFlags(&e1, cudaEventDisableTiming);
        cudaEventCreateWithFlags(&e2, cudaEventDisableTiming);
    }
};
static GcmStreams g_str;

// ---------------- launch -----------------------------------------------------
extern "C" void kernel_launch(void* const* d_in, const int* in_sizes, int n_in,
                              void* d_out, int out_size)
{
    const float* features  = (const float*)d_in[0];
    const float* adjacency = (const float*)d_in[1];
    const float* edge_w    = (const float*)d_in[2];
    const float* edge_b    = (const float*)d_in[3];
    const float* W         = (const float*)d_in[4];
    const float* bias      = (const float*)d_in[5];
    const float* gamma     = (const float*)d_in[6];
    const float* beta      = (const float*)d_in[7];
    float* out = (float*)d_out;

    unsigned char *av, *bv;
    __half *yv, *state;
    cudaGetSymbolAddress((void**)&av, g_a);
    cudaGetSymbolAddress((void**)&bv, g_b);
    cudaGetSymbolAddress((void**)&yv, g_y);
    cudaGetSymbolAddress((void**)&state, g_state);

    cudaFuncSetAttribute(gemm_kernel, cudaFuncAttributeMaxDynamicSharedMemorySize,
                         GEMM_SMEM_DYN);

    const size_t bl = (size_t)KCHUNKS * NTILES * BTILE_BYTES;
    cudaStream_t s1 = g_str.s1, s2 = g_str.s2;

    cudaEventRecord(g_str.e_root, 0);
    cudaStreamWaitEvent(s1, g_str.e_root, 0);
    cudaStreamWaitEvent(s2, g_str.e_root, 0);

    // ---- chain X on s1 -------------------------------------------------------
    wconv_kernel<<<256, 256, 0, s1>>>(W);
    cudaEventRecord(g_str.e_w, s1);
    mix_kernel<<<G1, 256, 0, s1>>>(features, adjacency, edge_w, edge_b, 0);
    gemm_kernel<<<MT1 * NTILES, 256, GEMM_SMEM_DYN, s1>>>(av, bv, yv, 0);
    lnmix_kernel<<<G1, 256, 0, s1>>>(yv, features, gamma, beta, bias, 0);
    gemm_kernel<<<MT1 * NTILES, 256, GEMM_SMEM_DYN, s1>>>(av, bv + bl, yv, 0);
    ln_kernel<<<LNB1, 256, 0, s1>>>(yv, state, out, gamma + D_, beta + D_,
                                    bias + D_, 0);
    cudaEventRecord(g_str.e1, s1);

    // ---- chain Y on s2 -------------------------------------------------------
    mix_kernel<<<G2, 256, 0, s2>>>(features, adjacency, edge_w, edge_b, G1);
    cudaStreamWaitEvent(s2, g_str.e_w, 0);
    gemm_kernel<<<MT2 * NTILES, 256, GEMM_SMEM_DYN, s2>>>(av, bv, yv, MT1);
    lnmix_kernel<<<G2, 256, 0, s2>>>(yv, features, gamma, beta, bias, G1);
    gemm_kernel<<<MT2 * NTILES, 256, GEMM_SMEM_DYN, s2>>>(av, bv + bl, yv, MT1);
    ln_kernel<<<LNB2, 256, 0, s2>>>(yv, state, out, gamma + D_, beta + D_,
                                    bias + D_, LNB1);
    cudaEventRecord(g_str.e2, s2);

    cudaStreamWaitEvent(0, g_str.e1, 0);
    cudaStreamWaitEvent(0, g_str.e2, 0);
}